// round 4
// baseline (speedup 1.0000x reference)
#include <cuda_runtime.h>

#define N 128
#define D 8192
#define KSLICES 8
#define KSLICE (D / KSLICES)   // 1024

__device__ float g_sq1[N], g_sq2[N];
__device__ float g_part[KSLICES * N * N];
__device__ float g_GM[N * N];

// ---------------------------------------------------------------------------
// K1: squared row norms of both batches. 256 blocks (128 rows x 2 tensors).
// ---------------------------------------------------------------------------
__global__ void sq_kernel(const float* __restrict__ f1, const float* __restrict__ f2) {
    int b = blockIdx.x;
    const float* f = (b < N) ? (f1 + (size_t)b * D) : (f2 + (size_t)(b - N) * D);
    const float4* f4 = (const float4*)f;
    int tid = threadIdx.x;
    float s = 0.f;
    #pragma unroll
    for (int it = 0; it < D / 4 / 256; it++) {
        float4 v = f4[tid + it * 256];
        s += v.x * v.x + v.y * v.y + v.z * v.z + v.w * v.w;
    }
    #pragma unroll
    for (int o = 16; o; o >>= 1) s += __shfl_xor_sync(0xffffffffu, s, o);
    __shared__ float ws[8];
    if ((tid & 31) == 0) ws[tid >> 5] = s;
    __syncthreads();
    if (tid < 8) {
        float t = ws[tid];
        #pragma unroll
        for (int o = 4; o; o >>= 1) t += __shfl_xor_sync(0xffu, t, o);
        if (tid == 0) { if (b < N) g_sq1[b] = t; else g_sq2[b - N] = t; }
    }
}

// ---------------------------------------------------------------------------
// K2: deterministic split-K GEMM: partial dot(f1_i, f2_j) per K-slice.
// grid (4,4,8): 32x32 output tile, 1024-K slice. block (32,8), 4 outputs/thread.
// ---------------------------------------------------------------------------
__global__ void dot_kernel(const float* __restrict__ f1, const float* __restrict__ f2) {
    __shared__ float As[32][36];   // stride 36: 16B-aligned rows, conflict-free f4 reads
    __shared__ float Bs[32][36];
    int tx = threadIdx.x;          // 0..31 : col within j-tile
    int ty = threadIdx.y;          // 0..7
    int ti = blockIdx.y * 32;
    int tj = blockIdx.x * 32;
    int k0 = blockIdx.z * KSLICE;

    float acc[4] = {0.f, 0.f, 0.f, 0.f};
    for (int kk = 0; kk < KSLICE; kk += 32) {
        #pragma unroll
        for (int q = 0; q < 4; q++) {
            int r = ty + q * 8;
            As[r][tx] = f1[(size_t)(ti + r) * D + k0 + kk + tx];
            Bs[r][tx] = f2[(size_t)(tj + r) * D + k0 + kk + tx];
        }
        __syncthreads();
        #pragma unroll
        for (int c = 0; c < 32; c += 4) {
            float4 b4 = *(const float4*)&Bs[tx][c];
            #pragma unroll
            for (int m = 0; m < 4; m++) {
                float4 a4 = *(const float4*)&As[ty + m * 8][c];
                acc[m] += a4.x * b4.x + a4.y * b4.y + a4.z * b4.z + a4.w * b4.w;
            }
        }
        __syncthreads();
    }
    #pragma unroll
    for (int m = 0; m < 4; m++)
        g_part[blockIdx.z * (N * N) + (size_t)(ti + ty + m * 8) * N + tj + tx] = acc[m];
}

// ---------------------------------------------------------------------------
// K3: finalize GM[i][j] = sim ? max(0,d2) : max(0, 200-d2)
// ---------------------------------------------------------------------------
__global__ void gm_kernel(const int* __restrict__ t1, const int* __restrict__ t2) {
    int idx = blockIdx.x * 256 + threadIdx.x;   // 64 blocks * 256 = 16384
    int i = idx >> 7, j = idx & (N - 1);
    float dot = 0.f;
    #pragma unroll
    for (int s = 0; s < KSLICES; s++) dot += g_part[s * (N * N) + idx];
    float d2 = g_sq1[i] - 2.f * dot + g_sq2[j];
    float gm = (t1[i] == t2[j]) ? fmaxf(0.f, d2) : fmaxf(0.f, 200.f - d2);
    g_GM[idx] = gm;
}

// ---------------------------------------------------------------------------
// K4: exact Hungarian (min-cost on -GM) on a single warp.
// Lane owns columns c = lane + 32*t (t=0..3): v, minv, used in registers.
// Warm start: row/col reduction + greedy tight matching, then e-maxx
// augmentation for remaining rows. Argmin via REDUX on order-preserving key.
// ---------------------------------------------------------------------------
__device__ __forceinline__ unsigned fkey(float f) {
    unsigned u = __float_as_uint(f);
    return (u & 0x80000000u) ? ~u : (u | 0x80000000u);
}

__global__ void hungarian_kernel(float* __restrict__ out) {
    extern __shared__ unsigned char s_raw[];
    float* cost = (float*)s_raw;           // N*N floats (64 KB)
    float* u_s  = cost + N * N;            // N+1 (rows 1..N)
    int*   p_s  = (int*)(u_s + (N + 1));   // N+1 (col -> matched row, 0 = free)
    int*   way_s = p_s + (N + 1);          // N+1
    int*   rm_s  = way_s + (N + 1);        // N+1 (row matched flags)

    const unsigned FULL = 0xffffffffu;
    int lane = threadIdx.x;

    for (int idx = lane; idx < N * N; idx += 32) cost[idx] = -g_GM[idx];
    for (int idx = lane; idx <= N; idx += 32) { p_s[idx] = 0; way_s[idx] = 0; rm_s[idx] = 0; }
    __syncwarp();

    // u[i] = min_j cost[i][j]  (lane-skewed column order: conflict-free)
    #pragma unroll
    for (int t = 0; t < 4; t++) {
        int r = lane + 32 * t;
        float m = 1e30f;
        #pragma unroll 4
        for (int cc = 0; cc < N; cc++) {
            int c = (cc + lane) & (N - 1);
            m = fminf(m, cost[r * N + c]);
        }
        u_s[r + 1] = m;
    }
    __syncwarp();

    // v[c] = min_i (cost[i][c] - u[i])   (col access: bank = lane, conflict-free)
    float v[4];
    #pragma unroll
    for (int t = 0; t < 4; t++) {
        int c = lane + 32 * t;
        float m = 1e30f;
        for (int r = 0; r < N; r++) m = fminf(m, cost[r * N + c] - u_s[r + 1]);
        v[t] = m;
    }
    __syncwarp();

    // Greedy: match each row to a tight, free column if one exists.
    for (int i = 1; i <= N; i++) {
        unsigned cand = 0xffffffffu;
        float ui = u_s[i];
        #pragma unroll
        for (int t = 0; t < 4; t++) {
            int c = lane + 32 * t;
            if (p_s[c + 1] == 0) {
                float cur = (cost[(i - 1) * N + c] - ui) - v[t];
                if (cur <= 0.0f) cand = min(cand, (unsigned)c);
            }
        }
        unsigned cm = __reduce_min_sync(FULL, cand);
        if (cm != 0xffffffffu && lane == 0) { p_s[cm + 1] = i; rm_s[i] = 1; }
        __syncwarp();
    }

    // Augment remaining rows (e-maxx KM with column-0 virtual start).
    for (int i = 1; i <= N; i++) {
        if (rm_s[i]) continue;
        float minv[4] = {1e30f, 1e30f, 1e30f, 1e30f};
        unsigned usedmask = 0;
        if (lane == 0) p_s[0] = i;
        int j0 = 0;
        __syncwarp();

        for (int guard = 0; guard < N + 2; guard++) {
            if (j0 > 0) {
                int c = j0 - 1;
                if ((c & 31) == lane) usedmask |= 1u << (c >> 5);
            }
            int i0 = p_s[j0];
            float ui0 = u_s[i0];
            float best = 1e30f; int bestc = 0;
            #pragma unroll
            for (int t = 0; t < 4; t++) {
                if (!((usedmask >> t) & 1)) {
                    int c = lane + 32 * t;
                    float cur = (cost[(i0 - 1) * N + c] - ui0) - v[t];
                    if (cur < minv[t]) { minv[t] = cur; way_s[c + 1] = j0; }
                    if (minv[t] < best) { best = minv[t]; bestc = c; }
                }
            }
            unsigned key = fkey(best);
            unsigned rmin = __reduce_min_sync(FULL, key);
            unsigned ball = __ballot_sync(FULL, key == rmin);
            int win = __ffs(ball) - 1;
            float delta = __shfl_sync(FULL, best, win);
            int j1 = __shfl_sync(FULL, bestc, win) + 1;

            #pragma unroll
            for (int t = 0; t < 4; t++) {
                if ((usedmask >> t) & 1) {
                    v[t] -= delta;
                    int pr = p_s[lane + 32 * t + 1];
                    u_s[pr] += delta;          // distinct rows per used col: race-free
                } else {
                    minv[t] -= delta;
                }
            }
            if (lane == 0) u_s[i] += delta;    // virtual column 0 (p[0] = i)
            j0 = j1;
            __syncwarp();
            if (p_s[j0] == 0) break;           // free column reached
        }

        if (lane == 0) {
            int jj = j0;
            while (jj) { int j1 = way_s[jj]; p_s[jj] = p_s[j1]; jj = j1; }
            rm_s[i] = 1;
        }
        __syncwarp();
    }

    // loss = (1/N) * sum of matched GM = -(1/N) * sum of matched cost
    float s = 0.f;
    #pragma unroll
    for (int t = 0; t < 4; t++) {
        int c = lane + 32 * t;
        int r = p_s[c + 1];
        s += cost[(r - 1) * N + c];
    }
    #pragma unroll
    for (int o = 16; o; o >>= 1) s += __shfl_xor_sync(FULL, s, o);
    if (lane == 0) out[0] = -s * (1.0f / N);
}

// ---------------------------------------------------------------------------
extern "C" void kernel_launch(void* const* d_in, const int* in_sizes, int n_in,
                              void* d_out, int out_size) {
    const float* f1 = (const float*)d_in[0];
    const float* f2 = (const float*)d_in[1];
    const int*   t1 = (const int*)d_in[2];
    const int*   t2 = (const int*)d_in[3];
    float* out = (float*)d_out;

    sq_kernel<<<256, 256>>>(f1, f2);
    dot_kernel<<<dim3(4, 4, KSLICES), dim3(32, 8)>>>(f1, f2);
    gm_kernel<<<64, 256>>>(t1, t2);

    size_t smem = (size_t)N * N * sizeof(float) + 4 * (N + 1) * sizeof(int);
    cudaFuncSetAttribute(hungarian_kernel,
                         cudaFuncAttributeMaxDynamicSharedMemorySize, (int)smem);
    hungarian_kernel<<<1, 32, smem>>>(out);
}

// round 9
// speedup vs baseline: 14.6022x; 14.6022x over previous
#include <cuda_runtime.h>

#define N 128
#define D 8192
#define KSLICES 32
#define KSLICE (D / KSLICES)   // 256

__device__ float g_sq1[N], g_sq2[N];
__device__ float g_part[KSLICES * N * N];
__device__ float g_GM[N * N];
__device__ int   g_flag;           // nonzero => cross-label GM entry != 0
__device__ int   g_need_fallback;  // set by assign_kernel

// ---------------------------------------------------------------------------
// K1: squared row norms of both batches. 256 blocks (128 rows x 2 tensors).
// Also resets g_flag for this call (runs before K3 in stream order).
// ---------------------------------------------------------------------------
__global__ void sq_kernel(const float* __restrict__ f1, const float* __restrict__ f2) {
    if (blockIdx.x == 0 && threadIdx.x == 0) g_flag = 0;
    int b = blockIdx.x;
    const float* f = (b < N) ? (f1 + (size_t)b * D) : (f2 + (size_t)(b - N) * D);
    const float4* f4 = (const float4*)f;
    int tid = threadIdx.x;
    float s = 0.f;
    #pragma unroll
    for (int it = 0; it < D / 4 / 256; it++) {
        float4 v = f4[tid + it * 256];
        s += v.x * v.x + v.y * v.y + v.z * v.z + v.w * v.w;
    }
    #pragma unroll
    for (int o = 16; o; o >>= 1) s += __shfl_xor_sync(0xffffffffu, s, o);
    __shared__ float ws[8];
    if ((tid & 31) == 0) ws[tid >> 5] = s;
    __syncthreads();
    if (tid < 8) {
        float t = ws[tid];
        #pragma unroll
        for (int o = 4; o; o >>= 1) t += __shfl_xor_sync(0xffu, t, o);
        if (tid == 0) { if (b < N) g_sq1[b] = t; else g_sq2[b - N] = t; }
    }
}

// ---------------------------------------------------------------------------
// K2: deterministic split-K GEMM: partial dot(f1_i, f2_j) per K-slice.
// grid (4,4,32): 32x32 output tile, 256-K slice. block (32,8), 4 outputs/thread.
// ---------------------------------------------------------------------------
__global__ void dot_kernel(const float* __restrict__ f1, const float* __restrict__ f2) {
    __shared__ float As[32][36];
    __shared__ float Bs[32][36];
    int tx = threadIdx.x;
    int ty = threadIdx.y;
    int ti = blockIdx.y * 32;
    int tj = blockIdx.x * 32;
    int k0 = blockIdx.z * KSLICE;

    float acc[4] = {0.f, 0.f, 0.f, 0.f};
    for (int kk = 0; kk < KSLICE; kk += 32) {
        #pragma unroll
        for (int q = 0; q < 4; q++) {
            int r = ty + q * 8;
            As[r][tx] = f1[(size_t)(ti + r) * D + k0 + kk + tx];
            Bs[r][tx] = f2[(size_t)(tj + r) * D + k0 + kk + tx];
        }
        __syncthreads();
        #pragma unroll
        for (int c = 0; c < 32; c += 4) {
            float4 b4 = *(const float4*)&Bs[tx][c];
            #pragma unroll
            for (int m = 0; m < 4; m++) {
                float4 a4 = *(const float4*)&As[ty + m * 8][c];
                acc[m] += a4.x * b4.x + a4.y * b4.y + a4.z * b4.z + a4.w * b4.w;
            }
        }
        __syncthreads();
    }
    #pragma unroll
    for (int m = 0; m < 4; m++)
        g_part[blockIdx.z * (N * N) + (size_t)(ti + ty + m * 8) * N + tj + tx] = acc[m];
}

// ---------------------------------------------------------------------------
// K3: finalize GM[i][j]; flag if any cross-label GM entry is nonzero.
// ---------------------------------------------------------------------------
__global__ void gm_kernel(const int* __restrict__ t1, const int* __restrict__ t2) {
    int idx = blockIdx.x * 256 + threadIdx.x;   // 64 blocks * 256 = 16384
    int i = idx >> 7, j = idx & (N - 1);
    float dot = 0.f;
    #pragma unroll
    for (int s = 0; s < KSLICES; s++) dot += g_part[s * (N * N) + idx];
    float d2 = g_sq1[i] - 2.f * dot + g_sq2[j];
    bool same = (t1[i] == t2[j]);
    float gm = same ? fmaxf(0.f, d2) : fmaxf(0.f, 200.f - d2);
    g_GM[idx] = gm;
    if (!same && gm != 0.f) atomicOr(&g_flag, 1);
}

// ---------------------------------------------------------------------------
// order-preserving float -> u32 key for min reductions
// ---------------------------------------------------------------------------
__device__ __forceinline__ unsigned fkey(float f) {
    unsigned u = __float_as_uint(f);
    return (u & 0x80000000u) ? ~u : (u | 0x80000000u);
}

// ---------------------------------------------------------------------------
// K4: block-decomposed assignment. Since all cross-label GM entries are
// exactly 0 (verified; else fallback), the optimal plan decomposes into 16
// independent rectangular max-weight assignments, one per label. One warp
// per label runs an exact e-maxx Hungarian on its (padded-square, n<=32)
// block with one column per lane. 16 warps run concurrently in one CTA.
// ---------------------------------------------------------------------------
__global__ void assign_kernel(const int* __restrict__ t1, const int* __restrict__ t2,
                              float* __restrict__ out) {
    extern __shared__ unsigned char raw[];
    float* tile   = (float*)raw;                 // 16 * 1024 floats (64 KB)
    int*   rows   = (int*)(tile + 16 * 1024);    // 16 * 32
    int*   cols   = rows + 16 * 32;              // 16 * 32
    float* u_all  = (float*)(cols + 16 * 32);    // 16 * 34
    int*   p_all  = (int*)(u_all + 16 * 34);     // 16 * 34
    int*   way_all = p_all + 16 * 34;            // 16 * 34
    int*   t1s    = way_all + 16 * 34;           // 128
    int*   t2s    = t1s + 128;                   // 128
    int*   rc     = t2s + 128;                   // 32
    float* vals   = (float*)(rc + 32);           // 16
    int*   s_need = (int*)(vals + 16);           // 1

    const unsigned FULL = 0xffffffffu;
    int tid = threadIdx.x, lane = tid & 31, w = tid >> 5;

    if (tid < 128) { t1s[tid] = t1[tid]; t2s[tid] = t2[tid]; }
    __syncthreads();

    // Bucket rows/cols of label w (deterministic via ballot prefix).
    int r = 0, c = 0;
    #pragma unroll
    for (int ch = 0; ch < 4; ch++) {
        int e1 = t1s[ch * 32 + lane];
        unsigned b1 = __ballot_sync(FULL, e1 == w);
        if (e1 == w) {
            int pos = r + __popc(b1 & ((1u << lane) - 1u));
            if (pos < 32) rows[w * 32 + pos] = ch * 32 + lane;
        }
        r += __popc(b1);
        int e2 = t2s[ch * 32 + lane];
        unsigned b2 = __ballot_sync(FULL, e2 == w);
        if (e2 == w) {
            int pos = c + __popc(b2 & ((1u << lane) - 1u));
            if (pos < 32) cols[w * 32 + pos] = ch * 32 + lane;
        }
        c += __popc(b2);
    }
    if (lane == 0) { rc[w * 2] = r; rc[w * 2 + 1] = c; }
    __syncthreads();

    if (tid == 0) {
        int need = (g_flag != 0);
        int sr = 0, sc = 0;
        for (int L = 0; L < 16; L++) {
            int rr = rc[L * 2], cc = rc[L * 2 + 1];
            sr += rr; sc += cc;
            if (rr > 32 || cc > 32) need = 1;
        }
        if (sr != N || sc != N) need = 1;   // catches out-of-range labels too
        s_need[0] = need;
        g_need_fallback = need;
    }
    __syncthreads();
    if (s_need[0]) return;

    int n = max(r, c);
    float val = 0.f;
    if (r > 0 && c > 0) {
        float* C     = tile + w * 1024;       // C[i*32 + j]
        float* u_w   = u_all + w * 34;
        int*   p_w   = p_all + w * 34;
        int*   way_w = way_all + w * 34;

        for (int i = 0; i < n; i++) {
            float cv = 0.f;
            if (i < r && lane < c) cv = -g_GM[rows[w * 32 + i] * N + cols[w * 32 + lane]];
            C[i * 32 + lane] = cv;
        }
        for (int idx = lane; idx <= n; idx += 32) { u_w[idx] = 0.f; p_w[idx] = 0; way_w[idx] = 0; }
        __syncwarp();

        float v = 0.f;   // potential of column `lane`
        int pcol = 0;    // p_w[lane+1], cached per augmentation phase
        for (int i = 1; i <= n; i++) {
            if (lane == 0) p_w[0] = i;
            float minv = 1e30f;
            bool used = false;
            int j0 = 0;
            __syncwarp();

            for (int guard = 0; guard < 40; guard++) {
                if (j0 > 0 && lane == j0 - 1) used = true;
                int i0 = p_w[j0];
                float ui0 = u_w[i0];
                float best = 1e30f;
                if (!used && lane < n) {
                    float cur = C[(i0 - 1) * 32 + lane] - ui0 - v;
                    if (cur < minv) { minv = cur; way_w[lane + 1] = j0; }
                    best = minv;
                }
                unsigned key = fkey(best);
                unsigned rmin = __reduce_min_sync(FULL, key);
                unsigned ball = __ballot_sync(FULL, key == rmin);
                int win = __ffs(ball) - 1;
                float delta = __shfl_sync(FULL, best, win);

                if (lane < n) {
                    if (used) { v -= delta; u_w[pcol] += delta; }  // distinct rows: race-free
                    else minv -= delta;
                }
                if (lane == 0) u_w[i] += delta;   // virtual column 0 (p_w[0] = i)
                j0 = win + 1;
                __syncwarp();
                if (p_w[j0] == 0) break;
            }

            if (lane == 0) {
                int jj = j0;
                while (jj) { int jn = way_w[jj]; p_w[jj] = p_w[jn]; jj = jn; }
            }
            __syncwarp();
            pcol = (lane + 1 <= n) ? p_w[lane + 1] : 0;
        }

        float s = 0.f;
        if (lane < n) { int pr = p_w[lane + 1]; s = C[(pr - 1) * 32 + lane]; }
        #pragma unroll
        for (int o = 16; o; o >>= 1) s += __shfl_xor_sync(FULL, s, o);
        val = -s;   // matched GM sum for this label block
    }
    if (lane == 0) vals[w] = val;
    __syncthreads();

    if (tid == 0) {
        float tot = 0.f;
        for (int L = 0; L < 16; L++) tot += vals[L];
        out[0] = tot * (1.0f / N);
    }
}

// ---------------------------------------------------------------------------
// K5: fallback — exact full 128x128 Hungarian on a single warp (the previous
// passing kernel). Runs only if the decomposition precondition failed.
// ---------------------------------------------------------------------------
__global__ void hungarian_fallback(float* __restrict__ out) {
    if (g_need_fallback == 0) return;

    extern __shared__ unsigned char s_raw[];
    float* cost = (float*)s_raw;           // N*N floats (64 KB)
    float* u_s  = cost + N * N;            // N+1
    int*   p_s  = (int*)(u_s + (N + 1));   // N+1
    int*   way_s = p_s + (N + 1);          // N+1
    int*   rm_s  = way_s + (N + 1);        // N+1

    const unsigned FULL = 0xffffffffu;
    int lane = threadIdx.x;

    for (int idx = lane; idx < N * N; idx += 32) cost[idx] = -g_GM[idx];
    for (int idx = lane; idx <= N; idx += 32) { p_s[idx] = 0; way_s[idx] = 0; rm_s[idx] = 0; }
    __syncwarp();

    #pragma unroll
    for (int t = 0; t < 4; t++) {
        int r = lane + 32 * t;
        float m = 1e30f;
        #pragma unroll 4
        for (int cc = 0; cc < N; cc++) {
            int c = (cc + lane) & (N - 1);
            m = fminf(m, cost[r * N + c]);
        }
        u_s[r + 1] = m;
    }
    __syncwarp();

    float v[4];
    #pragma unroll
    for (int t = 0; t < 4; t++) {
        int c = lane + 32 * t;
        float m = 1e30f;
        for (int r = 0; r < N; r++) m = fminf(m, cost[r * N + c] - u_s[r + 1]);
        v[t] = m;
    }
    __syncwarp();

    for (int i = 1; i <= N; i++) {
        unsigned cand = 0xffffffffu;
        float ui = u_s[i];
        #pragma unroll
        for (int t = 0; t < 4; t++) {
            int c = lane + 32 * t;
            if (p_s[c + 1] == 0) {
                float cur = (cost[(i - 1) * N + c] - ui) - v[t];
                if (cur <= 0.0f) cand = min(cand, (unsigned)c);
            }
        }
        unsigned cm = __reduce_min_sync(FULL, cand);
        if (cm != 0xffffffffu && lane == 0) { p_s[cm + 1] = i; rm_s[i] = 1; }
        __syncwarp();
    }

    for (int i = 1; i <= N; i++) {
        if (rm_s[i]) continue;
        float minv[4] = {1e30f, 1e30f, 1e30f, 1e30f};
        unsigned usedmask = 0;
        if (lane == 0) p_s[0] = i;
        int j0 = 0;
        __syncwarp();

        for (int guard = 0; guard < N + 2; guard++) {
            if (j0 > 0) {
                int c = j0 - 1;
                if ((c & 31) == lane) usedmask |= 1u << (c >> 5);
            }
            int i0 = p_s[j0];
            float ui0 = u_s[i0];
            float best = 1e30f; int bestc = 0;
            #pragma unroll
            for (int t = 0; t < 4; t++) {
                if (!((usedmask >> t) & 1)) {
                    int c = lane + 32 * t;
                    float cur = (cost[(i0 - 1) * N + c] - ui0) - v[t];
                    if (cur < minv[t]) { minv[t] = cur; way_s[c + 1] = j0; }
                    if (minv[t] < best) { best = minv[t]; bestc = c; }
                }
            }
            unsigned key = fkey(best);
            unsigned rmin = __reduce_min_sync(FULL, key);
            unsigned ball = __ballot_sync(FULL, key == rmin);
            int win = __ffs(ball) - 1;
            float delta = __shfl_sync(FULL, best, win);
            int j1 = __shfl_sync(FULL, bestc, win) + 1;

            #pragma unroll
            for (int t = 0; t < 4; t++) {
                if ((usedmask >> t) & 1) {
                    v[t] -= delta;
                    int pr = p_s[lane + 32 * t + 1];
                    u_s[pr] += delta;
                } else {
                    minv[t] -= delta;
                }
            }
            if (lane == 0) u_s[i] += delta;
            j0 = j1;
            __syncwarp();
            if (p_s[j0] == 0) break;
        }

        if (lane == 0) {
            int jj = j0;
            while (jj) { int j1 = way_s[jj]; p_s[jj] = p_s[j1]; jj = j1; }
            rm_s[i] = 1;
        }
        __syncwarp();
    }

    float s = 0.f;
    #pragma unroll
    for (int t = 0; t < 4; t++) {
        int c = lane + 32 * t;
        int r = p_s[c + 1];
        s += cost[(r - 1) * N + c];
    }
    #pragma unroll
    for (int o = 16; o; o >>= 1) s += __shfl_xor_sync(FULL, s, o);
    if (lane == 0) out[0] = -s * (1.0f / N);
}

// ---------------------------------------------------------------------------
extern "C" void kernel_launch(void* const* d_in, const int* in_sizes, int n_in,
                              void* d_out, int out_size) {
    const float* f1 = (const float*)d_in[0];
    const float* f2 = (const float*)d_in[1];
    const int*   t1 = (const int*)d_in[2];
    const int*   t2 = (const int*)d_in[3];
    float* out = (float*)d_out;

    sq_kernel<<<256, 256>>>(f1, f2);
    dot_kernel<<<dim3(4, 4, KSLICES), dim3(32, 8)>>>(f1, f2);
    gm_kernel<<<64, 256>>>(t1, t2);

    size_t smem_assign = (size_t)16 * 1024 * 4          // tiles
                       + 2 * 16 * 32 * 4                // rows, cols
                       + 3 * 16 * 34 * 4                // u, p, way
                       + 2 * 128 * 4                    // t1s, t2s
                       + 32 * 4 + 16 * 4 + 16;          // rc, vals, s_need + pad
    cudaFuncSetAttribute(assign_kernel,
                         cudaFuncAttributeMaxDynamicSharedMemorySize, (int)smem_assign);
    assign_kernel<<<1, 512, smem_assign>>>(t1, t2, out);

    size_t smem_fb = (size_t)N * N * sizeof(float) + 4 * (N + 1) * sizeof(int);
    cudaFuncSetAttribute(hungarian_fallback,
                         cudaFuncAttributeMaxDynamicSharedMemorySize, (int)smem_fb);
    hungarian_fallback<<<1, 32, smem_fb>>>(out);
}

// round 10
// speedup vs baseline: 17.3814x; 1.1903x over previous
#include <cuda_runtime.h>

#define N 128
#define D 8192
#define KSLICES 32
#define KSLICE (D / KSLICES)   // 256

__device__ float g_sq1[N], g_sq2[N];
__device__ float g_part[KSLICES * N * N];
__device__ float g_GM[N * N];
__device__ int   g_flag;           // nonzero => cross-label GM entry != 0

// ---------------------------------------------------------------------------
// K1: squared row norms of both batches. 256 blocks (128 rows x 2 tensors).
// ---------------------------------------------------------------------------
__global__ void sq_kernel(const float* __restrict__ f1, const float* __restrict__ f2) {
    if (blockIdx.x == 0 && threadIdx.x == 0) g_flag = 0;
    int b = blockIdx.x;
    const float* f = (b < N) ? (f1 + (size_t)b * D) : (f2 + (size_t)(b - N) * D);
    const float4* f4 = (const float4*)f;
    int tid = threadIdx.x;
    float s = 0.f;
    #pragma unroll
    for (int it = 0; it < D / 4 / 256; it++) {
        float4 v = f4[tid + it * 256];
        s += v.x * v.x + v.y * v.y + v.z * v.z + v.w * v.w;
    }
    #pragma unroll
    for (int o = 16; o; o >>= 1) s += __shfl_xor_sync(0xffffffffu, s, o);
    __shared__ float ws[8];
    if ((tid & 31) == 0) ws[tid >> 5] = s;
    __syncthreads();
    if (tid < 8) {
        float t = ws[tid];
        #pragma unroll
        for (int o = 4; o; o >>= 1) t += __shfl_xor_sync(0xffu, t, o);
        if (tid == 0) { if (b < N) g_sq1[b] = t; else g_sq2[b - N] = t; }
    }
}

// ---------------------------------------------------------------------------
// K2: deterministic split-K GEMM with packed f32x2 FMA along K.
// grid (4,4,32): 32x32 tile, 256-K slice. block (32,8), 4 outputs/thread.
// Accumulates (even-k, odd-k) partial sums in packed 64-bit registers.
// ---------------------------------------------------------------------------
__global__ void dot_kernel(const float* __restrict__ f1, const float* __restrict__ f2) {
    __shared__ float As[32][36];
    __shared__ float Bs[32][36];
    int tx = threadIdx.x;
    int ty = threadIdx.y;
    int ti = blockIdx.y * 32;
    int tj = blockIdx.x * 32;
    int k0 = blockIdx.z * KSLICE;

    unsigned long long accA[4] = {0ull, 0ull, 0ull, 0ull};
    unsigned long long accB[4] = {0ull, 0ull, 0ull, 0ull};

    for (int kk = 0; kk < KSLICE; kk += 32) {
        #pragma unroll
        for (int q = 0; q < 4; q++) {
            int r = ty + q * 8;
            As[r][tx] = f1[(size_t)(ti + r) * D + k0 + kk + tx];
            Bs[r][tx] = f2[(size_t)(tj + r) * D + k0 + kk + tx];
        }
        __syncthreads();
        #pragma unroll
        for (int c = 0; c < 32; c += 4) {
            unsigned long long b01 = *(const unsigned long long*)&Bs[tx][c];
            unsigned long long b23 = *(const unsigned long long*)&Bs[tx][c + 2];
            #pragma unroll
            for (int m = 0; m < 4; m++) {
                unsigned long long a01 = *(const unsigned long long*)&As[ty + m * 8][c];
                unsigned long long a23 = *(const unsigned long long*)&As[ty + m * 8][c + 2];
                asm("fma.rn.f32x2 %0, %1, %2, %0;" : "+l"(accA[m]) : "l"(a01), "l"(b01));
                asm("fma.rn.f32x2 %0, %1, %2, %0;" : "+l"(accB[m]) : "l"(a23), "l"(b23));
            }
        }
        __syncthreads();
    }
    #pragma unroll
    for (int m = 0; m < 4; m++) {
        float a_lo, a_hi, b_lo, b_hi;
        asm("mov.b64 {%0,%1}, %2;" : "=f"(a_lo), "=f"(a_hi) : "l"(accA[m]));
        asm("mov.b64 {%0,%1}, %2;" : "=f"(b_lo), "=f"(b_hi) : "l"(accB[m]));
        g_part[blockIdx.z * (N * N) + (size_t)(ti + ty + m * 8) * N + tj + tx] =
            (a_lo + a_hi) + (b_lo + b_hi);
    }
}

// ---------------------------------------------------------------------------
// K3: finalize GM[i][j]; flag if any cross-label GM entry is nonzero.
// ---------------------------------------------------------------------------
__global__ void gm_kernel(const int* __restrict__ t1, const int* __restrict__ t2) {
    int idx = blockIdx.x * 256 + threadIdx.x;
    int i = idx >> 7, j = idx & (N - 1);
    float dot = 0.f;
    #pragma unroll
    for (int s = 0; s < KSLICES; s++) dot += g_part[s * (N * N) + idx];
    float d2 = g_sq1[i] - 2.f * dot + g_sq2[j];
    bool same = (t1[i] == t2[j]);
    float gm = same ? fmaxf(0.f, d2) : fmaxf(0.f, 200.f - d2);
    g_GM[idx] = gm;
    if (!same && gm != 0.f) atomicOr(&g_flag, 1);
}

// ---------------------------------------------------------------------------
// order-preserving float <-> u32 keys for min reductions
// ---------------------------------------------------------------------------
__device__ __forceinline__ unsigned fkey(float f) {
    unsigned u = __float_as_uint(f);
    return (u & 0x80000000u) ? ~u : (u | 0x80000000u);
}
__device__ __forceinline__ float unfkey(unsigned k) {
    return __uint_as_float((k & 0x80000000u) ? (k ^ 0x80000000u) : ~k);
}

// ---------------------------------------------------------------------------
// K4: block-decomposed assignment (one warp per label, 16 warps in one CTA).
// Per warp: greedy warm start + deferred-potential (JV/Dijkstra) augmenting
// phases: NO smem writes and NO syncwarp in the inner loop; u/v updated once
// per phase from frozen per-lane d[] registers. Warp 0 runs the full 128x128
// Hungarian fallback if the zero-cross-block precondition fails.
// ---------------------------------------------------------------------------
__global__ void assign_kernel(const int* __restrict__ t1, const int* __restrict__ t2,
                              float* __restrict__ out) {
    extern __shared__ unsigned char raw[];
    float* tile    = (float*)raw;                 // 16 * 1024 floats (64 KB)
    int*   rows    = (int*)(tile + 16 * 1024);    // 16 * 32 (fallback: rm_s)
    int*   cols    = rows + 16 * 32;              // 16 * 32
    float* u_all   = (float*)(cols + 16 * 32);    // 16 * 34 (fallback: u_s)
    int*   p_all   = (int*)(u_all + 16 * 34);     // 16 * 34 (fallback: p_s)
    int*   way_all = p_all + 16 * 34;             // 16 * 34 (fallback: way_s)
    int*   t1s     = way_all + 16 * 34;           // 128
    int*   t2s     = t1s + 128;                   // 128
    int*   rc      = t2s + 128;                   // 32
    float* vals    = (float*)(rc + 32);           // 16
    int*   s_need  = (int*)(vals + 16);           // 1

    const unsigned FULL = 0xffffffffu;
    int tid = threadIdx.x, lane = tid & 31, w = tid >> 5;

    if (tid < 128) { t1s[tid] = t1[tid]; t2s[tid] = t2[tid]; }
    __syncthreads();

    // Bucket rows/cols of label w (deterministic via ballot prefix).
    int r = 0, c = 0;
    #pragma unroll
    for (int ch = 0; ch < 4; ch++) {
        int e1 = t1s[ch * 32 + lane];
        unsigned b1 = __ballot_sync(FULL, e1 == w);
        if (e1 == w) {
            int pos = r + __popc(b1 & ((1u << lane) - 1u));
            if (pos < 32) rows[w * 32 + pos] = ch * 32 + lane;
        }
        r += __popc(b1);
        int e2 = t2s[ch * 32 + lane];
        unsigned b2 = __ballot_sync(FULL, e2 == w);
        if (e2 == w) {
            int pos = c + __popc(b2 & ((1u << lane) - 1u));
            if (pos < 32) cols[w * 32 + pos] = ch * 32 + lane;
        }
        c += __popc(b2);
    }
    if (lane == 0) { rc[w * 2] = r; rc[w * 2 + 1] = c; }
    __syncthreads();

    if (tid == 0) {
        int need = (g_flag != 0);
        int sr = 0, sc = 0;
        for (int L = 0; L < 16; L++) {
            int rr = rc[L * 2], cc = rc[L * 2 + 1];
            sr += rr; sc += cc;
            if (rr > 32 || cc > 32) need = 1;
        }
        if (sr != N || sc != N) need = 1;
        s_need[0] = need;
    }
    __syncthreads();

    // ---------------- fallback: full 128x128 single-warp Hungarian ----------
    if (s_need[0]) {
        if (w != 0) return;
        float* cost  = tile;
        float* u_s   = u_all;
        int*   p_s   = p_all;
        int*   way_s = way_all;
        int*   rm_s  = rows;

        for (int idx = lane; idx < N * N; idx += 32) cost[idx] = -g_GM[idx];
        for (int idx = lane; idx <= N; idx += 32) { p_s[idx] = 0; way_s[idx] = 0; rm_s[idx] = 0; }
        __syncwarp();

        #pragma unroll
        for (int t = 0; t < 4; t++) {
            int rr = lane + 32 * t;
            float m = 1e30f;
            #pragma unroll 4
            for (int cc = 0; cc < N; cc++) {
                int ccc = (cc + lane) & (N - 1);
                m = fminf(m, cost[rr * N + ccc]);
            }
            u_s[rr + 1] = m;
        }
        __syncwarp();

        float v4[4];
        #pragma unroll
        for (int t = 0; t < 4; t++) {
            int cc = lane + 32 * t;
            float m = 1e30f;
            for (int rr = 0; rr < N; rr++) m = fminf(m, cost[rr * N + cc] - u_s[rr + 1]);
            v4[t] = m;
        }
        __syncwarp();

        for (int i = 1; i <= N; i++) {
            unsigned cand = 0xffffffffu;
            float ui = u_s[i];
            #pragma unroll
            for (int t = 0; t < 4; t++) {
                int cc = lane + 32 * t;
                if (p_s[cc + 1] == 0) {
                    float cur = (cost[(i - 1) * N + cc] - ui) - v4[t];
                    if (cur <= 0.0f) cand = min(cand, (unsigned)cc);
                }
            }
            unsigned cm = __reduce_min_sync(FULL, cand);
            if (cm != 0xffffffffu && lane == 0) { p_s[cm + 1] = i; rm_s[i] = 1; }
            __syncwarp();
        }

        for (int i = 1; i <= N; i++) {
            if (rm_s[i]) continue;
            float minv[4] = {1e30f, 1e30f, 1e30f, 1e30f};
            unsigned usedmask = 0;
            if (lane == 0) p_s[0] = i;
            int j0 = 0;
            __syncwarp();

            for (int guard = 0; guard < N + 2; guard++) {
                if (j0 > 0) {
                    int cc = j0 - 1;
                    if ((cc & 31) == lane) usedmask |= 1u << (cc >> 5);
                }
                int i0 = p_s[j0];
                float ui0 = u_s[i0];
                float best = 1e30f; int bestc = 0;
                #pragma unroll
                for (int t = 0; t < 4; t++) {
                    if (!((usedmask >> t) & 1)) {
                        int cc = lane + 32 * t;
                        float cur = (cost[(i0 - 1) * N + cc] - ui0) - v4[t];
                        if (cur < minv[t]) { minv[t] = cur; way_s[cc + 1] = j0; }
                        if (minv[t] < best) { best = minv[t]; bestc = cc; }
                    }
                }
                unsigned key = fkey(best);
                unsigned rmin = __reduce_min_sync(FULL, key);
                unsigned ball = __ballot_sync(FULL, key == rmin);
                int win = __ffs(ball) - 1;
                float delta = __shfl_sync(FULL, best, win);
                int j1 = __shfl_sync(FULL, bestc, win) + 1;

                #pragma unroll
                for (int t = 0; t < 4; t++) {
                    if ((usedmask >> t) & 1) {
                        v4[t] -= delta;
                        int pr = p_s[lane + 32 * t + 1];
                        u_s[pr] += delta;
                    } else {
                        minv[t] -= delta;
                    }
                }
                if (lane == 0) u_s[i] += delta;
                j0 = j1;
                __syncwarp();
                if (p_s[j0] == 0) break;
            }

            if (lane == 0) {
                int jj = j0;
                while (jj) { int j1 = way_s[jj]; p_s[jj] = p_s[j1]; jj = j1; }
                rm_s[i] = 1;
            }
            __syncwarp();
        }

        float s = 0.f;
        #pragma unroll
        for (int t = 0; t < 4; t++) {
            int cc = lane + 32 * t;
            int rr = p_s[cc + 1];
            s += cost[(rr - 1) * N + cc];
        }
        #pragma unroll
        for (int o = 16; o; o >>= 1) s += __shfl_xor_sync(FULL, s, o);
        if (lane == 0) out[0] = -s * (1.0f / N);
        return;
    }

    // ---------------- fast path: per-label JV Hungarian -----------------
    int n = max(r, c);
    float val = 0.f;
    if (r > 0 && c > 0) {
        float* C     = tile + w * 1024;       // C[i*32 + j]
        float* u_w   = u_all + w * 34;        // rows 1..n
        int*   p_w   = p_all + w * 34;        // col j (1..n) -> matched row (0 free)
        int*   way_w = way_all + w * 34;

        for (int i = 0; i < n; i++) {
            float cv = 0.f;
            if (i < r && lane < c) cv = -g_GM[rows[w * 32 + i] * N + cols[w * 32 + lane]];
            C[i * 32 + lane] = cv;
        }
        __syncwarp();

        // Row reduction: lane l owns row l (skewed scan, conflict-free).
        // Cost <= 0 everywhere, so extra zero columns never change the min.
        if (lane < n) {
            float m = 1e30f;
            #pragma unroll 4
            for (int k = 0; k < 32; k++) {
                int cidx = (k + lane) & 31;
                m = fminf(m, C[lane * 32 + cidx]);
            }
            u_w[lane + 1] = m;
        }
        __syncwarp();

        // Column reduction into register v (column = lane).
        float v = 0.f;
        if (lane < n) {
            float m = 1e30f;
            for (int i = 0; i < n; i++) m = fminf(m, C[i * 32 + lane] - u_w[i + 1]);
            v = m;
        }
        __syncwarp();

        // Greedy tight matching, all state warp-resident.
        int pcol = 0;               // matched row of this lane's column (0 free)
        unsigned rmmask = 0;        // matched-row bitmask (replicated)
        for (int i = 1; i <= n; i++) {
            float ui = u_w[i];
            bool tight = (lane < n) && (pcol == 0) &&
                         ((C[(i - 1) * 32 + lane] - ui) - v <= 0.0f);
            unsigned cand = tight ? (unsigned)lane : 0xffffffffu;
            unsigned cm = __reduce_min_sync(FULL, cand);
            if (cm != 0xffffffffu) {
                if ((int)cm == lane) pcol = i;
                rmmask |= 1u << (i - 1);
            }
        }
        p_w[lane + 1] = pcol;
        __syncwarp();

        // Augmenting phases (deferred potentials: pure Dijkstra inner loop).
        for (int f = 1; f <= n; f++) {
            if (rmmask & (1u << (f - 1))) continue;
            float uf = u_w[f];
            float d = (lane < n) ? (C[(f - 1) * 32 + lane] - uf) - v : 1e30f;
            int pred = 0;
            bool vis = false;
            int jf = 0; float Df = 0.f;

            for (int g = 0; g <= 32; g++) {
                unsigned key = vis ? 0xffffffffu : fkey(d);
                unsigned rmin = __reduce_min_sync(FULL, key);
                unsigned ball = __ballot_sync(FULL, key == rmin);
                int win = __ffs(ball) - 1;
                float dmin = unfkey(rmin);
                int i1 = p_w[win + 1];
                if (i1 == 0) { jf = win + 1; Df = dmin; break; }
                if (lane == win) vis = true;
                float ui1 = u_w[i1];
                float cij = C[(i1 - 1) * 32 + lane];
                if (!vis && lane < n) {
                    float cand = dmin + ((cij - ui1) - v);
                    if (cand < d) { d = cand; pred = win + 1; }
                }
            }

            // One-shot potential updates from frozen d[].
            if (vis) {
                u_w[pcol] += Df - d;     // distinct matched rows: race-free
                v += d - Df;
            }
            if (lane == 0) u_w[f] += Df;
            way_w[lane + 1] = pred;
            __syncwarp();

            if (lane == 0 && jf) {
                int jj = jf;
                while (jj) {
                    int jp = way_w[jj];
                    p_w[jj] = (jp == 0) ? f : p_w[jp];
                    jj = jp;
                }
            }
            __syncwarp();
            pcol = p_w[lane + 1];
        }

        float s = 0.f;
        if (lane < n) { int pr = p_w[lane + 1]; s = C[(pr - 1) * 32 + lane]; }
        #pragma unroll
        for (int o = 16; o; o >>= 1) s += __shfl_xor_sync(FULL, s, o);
        val = -s;
    }
    if (lane == 0) vals[w] = val;
    __syncthreads();

    if (tid == 0) {
        float tot = 0.f;
        for (int L = 0; L < 16; L++) tot += vals[L];
        out[0] = tot * (1.0f / N);
    }
}

// ---------------------------------------------------------------------------
extern "C" void kernel_launch(void* const* d_in, const int* in_sizes, int n_in,
                              void* d_out, int out_size) {
    const float* f1 = (const float*)d_in[0];
    const float* f2 = (const float*)d_in[1];
    const int*   t1 = (const int*)d_in[2];
    const int*   t2 = (const int*)d_in[3];
    float* out = (float*)d_out;

    sq_kernel<<<256, 256>>>(f1, f2);
    dot_kernel<<<dim3(4, 4, KSLICES), dim3(32, 8)>>>(f1, f2);
    gm_kernel<<<64, 256>>>(t1, t2);

    size_t smem_assign = (size_t)16 * 1024 * 4          // tiles
                       + 2 * 16 * 32 * 4                // rows, cols
                       + 3 * 16 * 34 * 4                // u, p, way
                       + 2 * 128 * 4                    // t1s, t2s
                       + 32 * 4 + 16 * 4 + 16;          // rc, vals, s_need + pad
    cudaFuncSetAttribute(assign_kernel,
                         cudaFuncAttributeMaxDynamicSharedMemorySize, (int)smem_assign);
    assign_kernel<<<1, 512, smem_assign>>>(t1, t2, out);
}

// round 11
// speedup vs baseline: 17.6661x; 1.0164x over previous
#include <cuda_runtime.h>

#define N 128
#define D 8192
#define KSLICES 32
#define KSLICE (D / KSLICES)   // 256

__device__ float g_sq1[N], g_sq2[N];
__device__ float g_part[KSLICES * N * N];
__device__ float g_GM[N * N];
__device__ int   g_flag;           // nonzero => cross-label GM entry != 0

// ---------------------------------------------------------------------------
// K1: fused split-K GEMM + row norms.
// grid (4,4,34): z<32 -> GEMM slice (32x32 tile, 256-K), packed f32x2 FMA.
//                z>=32 -> 32 norm blocks, one warp per row (256 rows).
// ---------------------------------------------------------------------------
__global__ void dotsq_kernel(const float* __restrict__ f1, const float* __restrict__ f2) {
    if (blockIdx.z >= KSLICES) {
        // ---- norm path ----
        int flat = (blockIdx.z - KSLICES) * 16 + blockIdx.y * 4 + blockIdx.x; // 0..31
        int tid  = threadIdx.y * 32 + threadIdx.x;
        int wid  = tid >> 5, lane = tid & 31;
        if (flat == 0 && tid == 0) g_flag = 0;
        int row = flat * 8 + wid;   // 0..255
        const float* f = (row < N) ? (f1 + (size_t)row * D) : (f2 + (size_t)(row - N) * D);
        const float4* f4 = (const float4*)f;
        float s = 0.f;
        #pragma unroll 8
        for (int it = 0; it < D / 4 / 32; it++) {
            float4 v = f4[lane + it * 32];
            s += v.x * v.x + v.y * v.y + v.z * v.z + v.w * v.w;
        }
        #pragma unroll
        for (int o = 16; o; o >>= 1) s += __shfl_xor_sync(0xffffffffu, s, o);
        if (lane == 0) { if (row < N) g_sq1[row] = s; else g_sq2[row - N] = s; }
        return;
    }

    // ---- GEMM path ----
    __shared__ float As[32][36];
    __shared__ float Bs[32][36];
    int tx = threadIdx.x;
    int ty = threadIdx.y;
    int ti = blockIdx.y * 32;
    int tj = blockIdx.x * 32;
    int k0 = blockIdx.z * KSLICE;

    unsigned long long accA[4] = {0ull, 0ull, 0ull, 0ull};
    unsigned long long accB[4] = {0ull, 0ull, 0ull, 0ull};

    for (int kk = 0; kk < KSLICE; kk += 32) {
        #pragma unroll
        for (int q = 0; q < 4; q++) {
            int r = ty + q * 8;
            As[r][tx] = f1[(size_t)(ti + r) * D + k0 + kk + tx];
            Bs[r][tx] = f2[(size_t)(tj + r) * D + k0 + kk + tx];
        }
        __syncthreads();
        #pragma unroll
        for (int c = 0; c < 32; c += 4) {
            unsigned long long b01 = *(const unsigned long long*)&Bs[tx][c];
            unsigned long long b23 = *(const unsigned long long*)&Bs[tx][c + 2];
            #pragma unroll
            for (int m = 0; m < 4; m++) {
                unsigned long long a01 = *(const unsigned long long*)&As[ty + m * 8][c];
                unsigned long long a23 = *(const unsigned long long*)&As[ty + m * 8][c + 2];
                asm("fma.rn.f32x2 %0, %1, %2, %0;" : "+l"(accA[m]) : "l"(a01), "l"(b01));
                asm("fma.rn.f32x2 %0, %1, %2, %0;" : "+l"(accB[m]) : "l"(a23), "l"(b23));
            }
        }
        __syncthreads();
    }
    #pragma unroll
    for (int m = 0; m < 4; m++) {
        float a_lo, a_hi, b_lo, b_hi;
        asm("mov.b64 {%0,%1}, %2;" : "=f"(a_lo), "=f"(a_hi) : "l"(accA[m]));
        asm("mov.b64 {%0,%1}, %2;" : "=f"(b_lo), "=f"(b_hi) : "l"(accB[m]));
        g_part[blockIdx.z * (N * N) + (size_t)(ti + ty + m * 8) * N + tj + tx] =
            (a_lo + a_hi) + (b_lo + b_hi);
    }
}

// ---------------------------------------------------------------------------
// K2: finalize GM[i][j]; flag if any cross-label GM entry is nonzero.
// ---------------------------------------------------------------------------
__global__ void gm_kernel(const int* __restrict__ t1, const int* __restrict__ t2) {
    int idx = blockIdx.x * 256 + threadIdx.x;
    int i = idx >> 7, j = idx & (N - 1);
    float dot = 0.f;
    #pragma unroll
    for (int s = 0; s < KSLICES; s++) dot += g_part[s * (N * N) + idx];
    float d2 = g_sq1[i] - 2.f * dot + g_sq2[j];
    bool same = (t1[i] == t2[j]);
    float gm = same ? fmaxf(0.f, d2) : fmaxf(0.f, 200.f - d2);
    g_GM[idx] = gm;
    if (!same && gm != 0.f) atomicOr(&g_flag, 1);
}

// ---------------------------------------------------------------------------
// order-preserving float <-> u32 keys for min reductions
// ---------------------------------------------------------------------------
__device__ __forceinline__ unsigned fkey(float f) {
    unsigned u = __float_as_uint(f);
    return (u & 0x80000000u) ? ~u : (u | 0x80000000u);
}
__device__ __forceinline__ float unfkey(unsigned k) {
    return __uint_as_float((k & 0x80000000u) ? (k ^ 0x80000000u) : ~k);
}

// ---------------------------------------------------------------------------
// K3: block-decomposed assignment (one warp per label, 16 warps in one CTA).
// Inner Dijkstra step has NO smem loads for matching state: lane-resident
// pcol/u_match served via shfl from the winner lane; only the C-row LDS
// remains. Greedy warm start runs on a precomputed tight-edge bitmask.
// Warp 0 runs the full 128x128 Hungarian fallback if the precondition fails.
// ---------------------------------------------------------------------------
__global__ void assign_kernel(const int* __restrict__ t1, const int* __restrict__ t2,
                              float* __restrict__ out) {
    extern __shared__ unsigned char raw[];
    float* tile    = (float*)raw;                 // 16 * 1024 floats (64 KB)
    int*   rows    = (int*)(tile + 16 * 1024);    // 16 * 32 (fallback: rm_s)
    int*   cols    = rows + 16 * 32;              // 16 * 32
    float* u_all   = (float*)(cols + 16 * 32);    // 16 * 34 (fallback: u_s)
    int*   p_all   = (int*)(u_all + 16 * 34);     // 16 * 34 (fallback: p_s)
    int*   way_all = p_all + 16 * 34;             // 16 * 34 (fallback: way_s)
    int*   t1s     = way_all + 16 * 34;           // 128
    int*   t2s     = t1s + 128;                   // 128
    int*   rc      = t2s + 128;                   // 32
    float* vals    = (float*)(rc + 32);           // 16
    int*   s_need  = (int*)(vals + 16);           // 1

    const unsigned FULL = 0xffffffffu;
    int tid = threadIdx.x, lane = tid & 31, w = tid >> 5;

    if (tid < 128) { t1s[tid] = t1[tid]; t2s[tid] = t2[tid]; }
    __syncthreads();

    // Bucket rows/cols of label w (deterministic via ballot prefix).
    int r = 0, c = 0;
    #pragma unroll
    for (int ch = 0; ch < 4; ch++) {
        int e1 = t1s[ch * 32 + lane];
        unsigned b1 = __ballot_sync(FULL, e1 == w);
        if (e1 == w) {
            int pos = r + __popc(b1 & ((1u << lane) - 1u));
            if (pos < 32) rows[w * 32 + pos] = ch * 32 + lane;
        }
        r += __popc(b1);
        int e2 = t2s[ch * 32 + lane];
        unsigned b2 = __ballot_sync(FULL, e2 == w);
        if (e2 == w) {
            int pos = c + __popc(b2 & ((1u << lane) - 1u));
            if (pos < 32) cols[w * 32 + pos] = ch * 32 + lane;
        }
        c += __popc(b2);
    }
    if (lane == 0) { rc[w * 2] = r; rc[w * 2 + 1] = c; }
    __syncthreads();

    if (tid == 0) {
        int need = (g_flag != 0);
        int sr = 0, sc = 0;
        for (int L = 0; L < 16; L++) {
            int rr = rc[L * 2], cc = rc[L * 2 + 1];
            sr += rr; sc += cc;
            if (rr > 32 || cc > 32) need = 1;
        }
        if (sr != N || sc != N) need = 1;
        s_need[0] = need;
    }
    __syncthreads();

    // ---------------- fallback: full 128x128 single-warp Hungarian ----------
    if (s_need[0]) {
        if (w != 0) return;
        float* cost  = tile;
        float* u_s   = u_all;
        int*   p_s   = p_all;
        int*   way_s = way_all;
        int*   rm_s  = rows;

        for (int idx = lane; idx < N * N; idx += 32) cost[idx] = -g_GM[idx];
        for (int idx = lane; idx <= N; idx += 32) { p_s[idx] = 0; way_s[idx] = 0; rm_s[idx] = 0; }
        __syncwarp();

        #pragma unroll
        for (int t = 0; t < 4; t++) {
            int rr = lane + 32 * t;
            float m = 1e30f;
            #pragma unroll 4
            for (int cc = 0; cc < N; cc++) {
                int ccc = (cc + lane) & (N - 1);
                m = fminf(m, cost[rr * N + ccc]);
            }
            u_s[rr + 1] = m;
        }
        __syncwarp();

        float v4[4];
        #pragma unroll
        for (int t = 0; t < 4; t++) {
            int cc = lane + 32 * t;
            float m = 1e30f;
            for (int rr = 0; rr < N; rr++) m = fminf(m, cost[rr * N + cc] - u_s[rr + 1]);
            v4[t] = m;
        }
        __syncwarp();

        for (int i = 1; i <= N; i++) {
            unsigned cand = 0xffffffffu;
            float ui = u_s[i];
            #pragma unroll
            for (int t = 0; t < 4; t++) {
                int cc = lane + 32 * t;
                if (p_s[cc + 1] == 0) {
                    float cur = (cost[(i - 1) * N + cc] - ui) - v4[t];
                    if (cur <= 0.0f) cand = min(cand, (unsigned)cc);
                }
            }
            unsigned cm = __reduce_min_sync(FULL, cand);
            if (cm != 0xffffffffu && lane == 0) { p_s[cm + 1] = i; rm_s[i] = 1; }
            __syncwarp();
        }

        for (int i = 1; i <= N; i++) {
            if (rm_s[i]) continue;
            float minv[4] = {1e30f, 1e30f, 1e30f, 1e30f};
            unsigned usedmask = 0;
            if (lane == 0) p_s[0] = i;
            int j0 = 0;
            __syncwarp();

            for (int guard = 0; guard < N + 2; guard++) {
                if (j0 > 0) {
                    int cc = j0 - 1;
                    if ((cc & 31) == lane) usedmask |= 1u << (cc >> 5);
                }
                int i0 = p_s[j0];
                float ui0 = u_s[i0];
                float best = 1e30f; int bestc = 0;
                #pragma unroll
                for (int t = 0; t < 4; t++) {
                    if (!((usedmask >> t) & 1)) {
                        int cc = lane + 32 * t;
                        float cur = (cost[(i0 - 1) * N + cc] - ui0) - v4[t];
                        if (cur < minv[t]) { minv[t] = cur; way_s[cc + 1] = j0; }
                        if (minv[t] < best) { best = minv[t]; bestc = cc; }
                    }
                }
                unsigned key = fkey(best);
                unsigned rmin = __reduce_min_sync(FULL, key);
                unsigned ball = __ballot_sync(FULL, key == rmin);
                int win = __ffs(ball) - 1;
                float delta = __shfl_sync(FULL, best, win);
                int j1 = __shfl_sync(FULL, bestc, win) + 1;

                #pragma unroll
                for (int t = 0; t < 4; t++) {
                    if ((usedmask >> t) & 1) {
                        v4[t] -= delta;
                        int pr = p_s[lane + 32 * t + 1];
                        u_s[pr] += delta;
                    } else {
                        minv[t] -= delta;
                    }
                }
                if (lane == 0) u_s[i] += delta;
                j0 = j1;
                __syncwarp();
                if (p_s[j0] == 0) break;
            }

            if (lane == 0) {
                int jj = j0;
                while (jj) { int j1 = way_s[jj]; p_s[jj] = p_s[j1]; jj = j1; }
                rm_s[i] = 1;
            }
            __syncwarp();
        }

        float s = 0.f;
        #pragma unroll
        for (int t = 0; t < 4; t++) {
            int cc = lane + 32 * t;
            int rr = p_s[cc + 1];
            s += cost[(rr - 1) * N + cc];
        }
        #pragma unroll
        for (int o = 16; o; o >>= 1) s += __shfl_xor_sync(FULL, s, o);
        if (lane == 0) out[0] = -s * (1.0f / N);
        return;
    }

    // ---------------- fast path: per-label JV Hungarian -----------------
    int n = max(r, c);
    float val = 0.f;
    if (r > 0 && c > 0) {
        float* C     = tile + w * 1024;       // C[i*32 + j]
        float* u_w   = u_all + w * 34;        // rows 1..n
        int*   p_w   = p_all + w * 34;        // col j (1..n) -> matched row (0 free)
        int*   way_w = way_all + w * 34;

        #pragma unroll 4
        for (int i = 0; i < n; i++) {
            float cv = 0.f;
            if (i < r && lane < c) cv = -g_GM[rows[w * 32 + i] * N + cols[w * 32 + lane]];
            C[i * 32 + lane] = cv;
        }
        __syncwarp();

        // Row reduction (lane = row; skewed scan, conflict-free).
        if (lane < n) {
            float m = 1e30f;
            #pragma unroll 4
            for (int k = 0; k < 32; k++) {
                int cidx = (k + lane) & 31;
                m = fminf(m, C[lane * 32 + cidx]);
            }
            u_w[lane + 1] = m;
        }
        __syncwarp();

        // Column reduction into register v, then tight-edge bitmask.
        float v = 0.f;
        unsigned tmask = 0;
        if (lane < n) {
            float m = 1e30f;
            #pragma unroll 4
            for (int i = 0; i < n; i++) m = fminf(m, C[i * 32 + lane] - u_w[i + 1]);
            v = m;
            #pragma unroll 4
            for (int i = 0; i < n; i++)
                if ((C[i * 32 + lane] - u_w[i + 1]) - v <= 0.0f) tmask |= 1u << i;
        }
        __syncwarp();

        // Greedy tight matching: pure ALU + REDUX, no LDS in the loop.
        int pcol = 0;               // matched row of this lane's column (0 free)
        unsigned rmmask = 0;        // matched-row bitmask (replicated)
        for (int i = 1; i <= n; i++) {
            bool avail = (pcol == 0) && ((tmask >> (i - 1)) & 1);
            unsigned cand = avail ? (unsigned)lane : 0xffffffffu;
            unsigned cm = __reduce_min_sync(FULL, cand);
            if (cm != 0xffffffffu) {
                if ((int)cm == lane) pcol = i;
                rmmask |= 1u << (i - 1);
            }
        }
        p_w[lane + 1] = pcol;
        __syncwarp();
        float u_match = pcol ? u_w[pcol] : 0.f;

        // Augmenting phases: deferred potentials, shfl-served matching state.
        for (int f = 1; f <= n; f++) {
            if (rmmask & (1u << (f - 1))) continue;
            float uf = u_w[f];
            float d = (lane < n) ? (C[(f - 1) * 32 + lane] - uf) - v : 1e30f;
            int pred = 0;
            bool vis = false;
            int jf = 0; float Df = 0.f;

            for (int g = 0; g <= 32; g++) {
                unsigned key = vis ? 0xffffffffu : fkey(d);
                unsigned rmin = __reduce_min_sync(FULL, key);
                unsigned ball = __ballot_sync(FULL, key == rmin);
                int win = __ffs(ball) - 1;
                int   i1  = __shfl_sync(FULL, pcol, win);
                float ui1 = __shfl_sync(FULL, u_match, win);
                float dmin = unfkey(rmin);
                if (i1 == 0) { jf = win + 1; Df = dmin; break; }
                if (lane == win) vis = true;
                float cij = C[(i1 - 1) * 32 + lane];
                if (!vis && lane < n) {
                    float cand = dmin + ((cij - ui1) - v);
                    if (cand < d) { d = cand; pred = win + 1; }
                }
            }

            // One-shot potential updates from frozen d[].
            if (vis) {
                u_w[pcol] += Df - d;     // distinct matched rows: race-free
                u_match   += Df - d;
                v += d - Df;
            }
            if (lane == 0) u_w[f] += Df;
            way_w[lane + 1] = pred;
            __syncwarp();

            if (lane == 0 && jf) {
                int jj = jf;
                while (jj) {
                    int jp = way_w[jj];
                    p_w[jj] = (jp == 0) ? f : p_w[jp];
                    jj = jp;
                }
            }
            __syncwarp();
            int np = p_w[lane + 1];
            if (np != pcol) { pcol = np; u_match = u_w[pcol]; }
        }

        float s = 0.f;
        if (lane < n) { int pr = p_w[lane + 1]; s = C[(pr - 1) * 32 + lane]; }
        #pragma unroll
        for (int o = 16; o; o >>= 1) s += __shfl_xor_sync(FULL, s, o);
        val = -s;
    }
    if (lane == 0) vals[w] = val;
    __syncthreads();

    if (tid == 0) {
        float tot = 0.f;
        for (int L = 0; L < 16; L++) tot += vals[L];
        out[0] = tot * (1.0f / N);
    }
}

// ---------------------------------------------------------------------------
extern "C" void kernel_launch(void* const* d_in, const int* in_sizes, int n_in,
                              void* d_out, int out_size) {
    const float* f1 = (const float*)d_in[0];
    const float* f2 = (const float*)d_in[1];
    const int*   t1 = (const int*)d_in[2];
    const int*   t2 = (const int*)d_in[3];
    float* out = (float*)d_out;

    dotsq_kernel<<<dim3(4, 4, KSLICES + 2), dim3(32, 8)>>>(f1, f2);
    gm_kernel<<<64, 256>>>(t1, t2);

    size_t smem_assign = (size_t)16 * 1024 * 4          // tiles
                       + 2 * 16 * 32 * 4                // rows, cols
                       + 3 * 16 * 34 * 4                // u, p, way
                       + 2 * 128 * 4                    // t1s, t2s
                       + 32 * 4 + 16 * 4 + 16;          // rc, vals, s_need + pad
    cudaFuncSetAttribute(assign_kernel,
                         cudaFuncAttributeMaxDynamicSharedMemorySize, (int)smem_assign);
    assign_kernel<<<1, 512, smem_assign>>>(t1, t2, out);
}

// round 12
// speedup vs baseline: 20.5145x; 1.1612x over previous
#include <cuda_runtime.h>

#define N 128
#define D 8192
#define KSLICES 32
#define KSLICE (D / KSLICES)   // 256

typedef unsigned long long ull;

__device__ float g_sq1[N], g_sq2[N];
__device__ float g_part[KSLICES * N * N];
__device__ float g_GM[N * N];
__device__ int   g_flag;           // nonzero => cross-label GM entry != 0

// ---------------------------------------------------------------------------
// K1: fused split-K GEMM + row norms.
// grid (2,2,34): z<32 -> GEMM: 64x64 output tile, 256-K slice, 256 threads,
//                16 outputs/thread, f32x2 FMA with k-pair-packed B in smem.
//                z>=32 -> 8 norm blocks (32 rows each, warp per 4 rows).
// ---------------------------------------------------------------------------
__global__ void dotsq_kernel(const float* __restrict__ f1, const float* __restrict__ f2) {
    if (blockIdx.z >= KSLICES) {
        // ---- norm path ----
        int flat = (blockIdx.z - KSLICES) * 4 + blockIdx.y * 2 + blockIdx.x; // 0..7
        int tid  = threadIdx.x;
        int wid  = tid >> 5, lane = tid & 31;
        if (flat == 0 && tid == 0) g_flag = 0;
        #pragma unroll
        for (int rr = 0; rr < 4; rr++) {
            int row = flat * 32 + wid * 4 + rr;   // 0..255
            const float* f = (row < N) ? (f1 + (size_t)row * D)
                                       : (f2 + (size_t)(row - N) * D);
            const float4* f4 = (const float4*)f;
            float s = 0.f;
            #pragma unroll 8
            for (int it = 0; it < D / 4 / 32; it++) {
                float4 v = f4[lane + it * 32];
                s += v.x * v.x + v.y * v.y + v.z * v.z + v.w * v.w;
            }
            #pragma unroll
            for (int o = 16; o; o >>= 1) s += __shfl_xor_sync(0xffffffffu, s, o);
            if (lane == 0) { if (row < N) g_sq1[row] = s; else g_sq2[row - N] = s; }
        }
        return;
    }

    // ---- GEMM path ----
    __shared__ float  As[64][36];      // [i][k], 8B-aligned float2 rows
    __shared__ float2 Bs[16][64];      // [k/2][j] : (k even, k odd) packed

    int tid = threadIdx.x;             // 0..255
    int jx = tid & 15;                 // j group (4 cols)
    int iy = tid >> 4;                 // i group (4 rows)
    int ti = blockIdx.y * 64;
    int tj = blockIdx.x * 64;
    int k0 = blockIdx.z * KSLICE;

    ull acc[4][4];
    #pragma unroll
    for (int m = 0; m < 4; m++)
        #pragma unroll
        for (int jj = 0; jj < 4; jj++) acc[m][jj] = 0ull;

    int ra = tid >> 3, kq = (tid & 7) * 4;      // A-load mapping
    int jb = tid & 63, kh = (tid >> 6) * 8;     // B-load mapping

    for (int kk = 0; kk < KSLICE; kk += 32) {
        float4 v0 = *(const float4*)&f1[(size_t)(ti + ra) * D + k0 + kk + kq];
        float4 v1 = *(const float4*)&f1[(size_t)(ti + ra + 32) * D + k0 + kk + kq];
        As[ra][kq]      = v0.x; As[ra][kq + 1]      = v0.y;
        As[ra][kq + 2]  = v0.z; As[ra][kq + 3]      = v0.w;
        As[ra + 32][kq]     = v1.x; As[ra + 32][kq + 1] = v1.y;
        As[ra + 32][kq + 2] = v1.z; As[ra + 32][kq + 3] = v1.w;

        float4 w0 = *(const float4*)&f2[(size_t)(tj + jb) * D + k0 + kk + kh];
        float4 w1 = *(const float4*)&f2[(size_t)(tj + jb) * D + k0 + kk + kh + 4];
        Bs[(kh >> 1) + 0][jb] = make_float2(w0.x, w0.y);
        Bs[(kh >> 1) + 1][jb] = make_float2(w0.z, w0.w);
        Bs[(kh >> 1) + 2][jb] = make_float2(w1.x, w1.y);
        Bs[(kh >> 1) + 3][jb] = make_float2(w1.z, w1.w);
        __syncthreads();

        #pragma unroll
        for (int k2 = 0; k2 < 16; k2++) {
            ulonglong2 bp0 = *(const ulonglong2*)&Bs[k2][jx * 4];      // j0, j0+1
            ulonglong2 bp1 = *(const ulonglong2*)&Bs[k2][jx * 4 + 2];  // j0+2, j0+3
            ull a[4];
            #pragma unroll
            for (int m = 0; m < 4; m++)
                a[m] = *(const ull*)&As[iy * 4 + m][k2 * 2];
            #pragma unroll
            for (int m = 0; m < 4; m++) {
                asm("fma.rn.f32x2 %0, %1, %2, %0;" : "+l"(acc[m][0]) : "l"(a[m]), "l"(bp0.x));
                asm("fma.rn.f32x2 %0, %1, %2, %0;" : "+l"(acc[m][1]) : "l"(a[m]), "l"(bp0.y));
                asm("fma.rn.f32x2 %0, %1, %2, %0;" : "+l"(acc[m][2]) : "l"(a[m]), "l"(bp1.x));
                asm("fma.rn.f32x2 %0, %1, %2, %0;" : "+l"(acc[m][3]) : "l"(a[m]), "l"(bp1.y));
            }
        }
        __syncthreads();
    }

    #pragma unroll
    for (int m = 0; m < 4; m++) {
        int gi = ti + iy * 4 + m;
        float4 o;
        float lo, hi;
        asm("mov.b64 {%0,%1}, %2;" : "=f"(lo), "=f"(hi) : "l"(acc[m][0])); o.x = lo + hi;
        asm("mov.b64 {%0,%1}, %2;" : "=f"(lo), "=f"(hi) : "l"(acc[m][1])); o.y = lo + hi;
        asm("mov.b64 {%0,%1}, %2;" : "=f"(lo), "=f"(hi) : "l"(acc[m][2])); o.z = lo + hi;
        asm("mov.b64 {%0,%1}, %2;" : "=f"(lo), "=f"(hi) : "l"(acc[m][3])); o.w = lo + hi;
        *(float4*)&g_part[blockIdx.z * (N * N) + (size_t)gi * N + tj + jx * 4] = o;
    }
}

// ---------------------------------------------------------------------------
// K2: finalize GM[i][j]; flag if any cross-label GM entry is nonzero.
// ---------------------------------------------------------------------------
__global__ void gm_kernel(const int* __restrict__ t1, const int* __restrict__ t2) {
    int idx = blockIdx.x * 256 + threadIdx.x;
    int i = idx >> 7, j = idx & (N - 1);
    float dot = 0.f;
    #pragma unroll
    for (int s = 0; s < KSLICES; s++) dot += g_part[s * (N * N) + idx];
    float d2 = g_sq1[i] - 2.f * dot + g_sq2[j];
    bool same = (t1[i] == t2[j]);
    float gm = same ? fmaxf(0.f, d2) : fmaxf(0.f, 200.f - d2);
    g_GM[idx] = gm;
    if (!same && gm != 0.f) atomicOr(&g_flag, 1);
}

// ---------------------------------------------------------------------------
// order-preserving float <-> u32 keys for min reductions
// ---------------------------------------------------------------------------
__device__ __forceinline__ unsigned fkey(float f) {
    unsigned u = __float_as_uint(f);
    return (u & 0x80000000u) ? ~u : (u | 0x80000000u);
}
__device__ __forceinline__ float unfkey(unsigned k) {
    return __uint_as_float((k & 0x80000000u) ? (k ^ 0x80000000u) : ~k);
}

// ---------------------------------------------------------------------------
// K3: block-decomposed assignment (one warp per label, 16 warps in one CTA).
// Inner Dijkstra step: lane-resident pcol/u_match via shfl; only the C-row
// LDS remains. Warp 0 runs the full 128x128 fallback if precondition fails.
// ---------------------------------------------------------------------------
__global__ void assign_kernel(const int* __restrict__ t1, const int* __restrict__ t2,
                              float* __restrict__ out) {
    extern __shared__ unsigned char raw[];
    float* tile    = (float*)raw;                 // 16 * 1024 floats (64 KB)
    int*   rows    = (int*)(tile + 16 * 1024);    // 16 * 32 (fallback: rm_s)
    int*   cols    = rows + 16 * 32;              // 16 * 32
    float* u_all   = (float*)(cols + 16 * 32);    // 16 * 34 (fallback: u_s)
    int*   p_all   = (int*)(u_all + 16 * 34);     // 16 * 34 (fallback: p_s)
    int*   way_all = p_all + 16 * 34;             // 16 * 34 (fallback: way_s)
    int*   t1s     = way_all + 16 * 34;           // 128
    int*   t2s     = t1s + 128;                   // 128
    int*   rc      = t2s + 128;                   // 32
    float* vals    = (float*)(rc + 32);           // 16
    int*   s_need  = (int*)(vals + 16);           // 1

    const unsigned FULL = 0xffffffffu;
    int tid = threadIdx.x, lane = tid & 31, w = tid >> 5;

    if (tid < 128) { t1s[tid] = t1[tid]; t2s[tid] = t2[tid]; }
    __syncthreads();

    int r = 0, c = 0;
    #pragma unroll
    for (int ch = 0; ch < 4; ch++) {
        int e1 = t1s[ch * 32 + lane];
        unsigned b1 = __ballot_sync(FULL, e1 == w);
        if (e1 == w) {
            int pos = r + __popc(b1 & ((1u << lane) - 1u));
            if (pos < 32) rows[w * 32 + pos] = ch * 32 + lane;
        }
        r += __popc(b1);
        int e2 = t2s[ch * 32 + lane];
        unsigned b2 = __ballot_sync(FULL, e2 == w);
        if (e2 == w) {
            int pos = c + __popc(b2 & ((1u << lane) - 1u));
            if (pos < 32) cols[w * 32 + pos] = ch * 32 + lane;
        }
        c += __popc(b2);
    }
    if (lane == 0) { rc[w * 2] = r; rc[w * 2 + 1] = c; }
    __syncthreads();

    if (tid == 0) {
        int need = (g_flag != 0);
        int sr = 0, sc = 0;
        for (int L = 0; L < 16; L++) {
            int rr = rc[L * 2], cc = rc[L * 2 + 1];
            sr += rr; sc += cc;
            if (rr > 32 || cc > 32) need = 1;
        }
        if (sr != N || sc != N) need = 1;
        s_need[0] = need;
    }
    __syncthreads();

    // ---------------- fallback: full 128x128 single-warp Hungarian ----------
    if (s_need[0]) {
        if (w != 0) return;
        float* cost  = tile;
        float* u_s   = u_all;
        int*   p_s   = p_all;
        int*   way_s = way_all;
        int*   rm_s  = rows;

        for (int idx = lane; idx < N * N; idx += 32) cost[idx] = -g_GM[idx];
        for (int idx = lane; idx <= N; idx += 32) { p_s[idx] = 0; way_s[idx] = 0; rm_s[idx] = 0; }
        __syncwarp();

        #pragma unroll
        for (int t = 0; t < 4; t++) {
            int rr = lane + 32 * t;
            float m = 1e30f;
            #pragma unroll 4
            for (int cc = 0; cc < N; cc++) {
                int ccc = (cc + lane) & (N - 1);
                m = fminf(m, cost[rr * N + ccc]);
            }
            u_s[rr + 1] = m;
        }
        __syncwarp();

        float v4[4];
        #pragma unroll
        for (int t = 0; t < 4; t++) {
            int cc = lane + 32 * t;
            float m = 1e30f;
            for (int rr = 0; rr < N; rr++) m = fminf(m, cost[rr * N + cc] - u_s[rr + 1]);
            v4[t] = m;
        }
        __syncwarp();

        for (int i = 1; i <= N; i++) {
            unsigned cand = 0xffffffffu;
            float ui = u_s[i];
            #pragma unroll
            for (int t = 0; t < 4; t++) {
                int cc = lane + 32 * t;
                if (p_s[cc + 1] == 0) {
                    float cur = (cost[(i - 1) * N + cc] - ui) - v4[t];
                    if (cur <= 0.0f) cand = min(cand, (unsigned)cc);
                }
            }
            unsigned cm = __reduce_min_sync(FULL, cand);
            if (cm != 0xffffffffu && lane == 0) { p_s[cm + 1] = i; rm_s[i] = 1; }
            __syncwarp();
        }

        for (int i = 1; i <= N; i++) {
            if (rm_s[i]) continue;
            float minv[4] = {1e30f, 1e30f, 1e30f, 1e30f};
            unsigned usedmask = 0;
            if (lane == 0) p_s[0] = i;
            int j0 = 0;
            __syncwarp();

            for (int guard = 0; guard < N + 2; guard++) {
                if (j0 > 0) {
                    int cc = j0 - 1;
                    if ((cc & 31) == lane) usedmask |= 1u << (cc >> 5);
                }
                int i0 = p_s[j0];
                float ui0 = u_s[i0];
                float best = 1e30f; int bestc = 0;
                #pragma unroll
                for (int t = 0; t < 4; t++) {
                    if (!((usedmask >> t) & 1)) {
                        int cc = lane + 32 * t;
                        float cur = (cost[(i0 - 1) * N + cc] - ui0) - v4[t];
                        if (cur < minv[t]) { minv[t] = cur; way_s[cc + 1] = j0; }
                        if (minv[t] < best) { best = minv[t]; bestc = cc; }
                    }
                }
                unsigned key = fkey(best);
                unsigned rmin = __reduce_min_sync(FULL, key);
                unsigned ball = __ballot_sync(FULL, key == rmin);
                int win = __ffs(ball) - 1;
                float delta = __shfl_sync(FULL, best, win);
                int j1 = __shfl_sync(FULL, bestc, win) + 1;

                #pragma unroll
                for (int t = 0; t < 4; t++) {
                    if ((usedmask >> t) & 1) {
                        v4[t] -= delta;
                        int pr = p_s[lane + 32 * t + 1];
                        u_s[pr] += delta;
                    } else {
                        minv[t] -= delta;
                    }
                }
                if (lane == 0) u_s[i] += delta;
                j0 = j1;
                __syncwarp();
                if (p_s[j0] == 0) break;
            }

            if (lane == 0) {
                int jj = j0;
                while (jj) { int j1 = way_s[jj]; p_s[jj] = p_s[j1]; jj = j1; }
                rm_s[i] = 1;
            }
            __syncwarp();
        }

        float s = 0.f;
        #pragma unroll
        for (int t = 0; t < 4; t++) {
            int cc = lane + 32 * t;
            int rr = p_s[cc + 1];
            s += cost[(rr - 1) * N + cc];
        }
        #pragma unroll
        for (int o = 16; o; o >>= 1) s += __shfl_xor_sync(FULL, s, o);
        if (lane == 0) out[0] = -s * (1.0f / N);
        return;
    }

    // ---------------- fast path: per-label JV Hungarian -----------------
    int n = max(r, c);
    float val = 0.f;
    if (r > 0 && c > 0) {
        float* C     = tile + w * 1024;       // C[i*32 + j]
        float* u_w   = u_all + w * 34;        // rows 1..n
        int*   p_w   = p_all + w * 34;        // col j (1..n) -> matched row (0 free)
        int*   way_w = way_all + w * 34;

        #pragma unroll 4
        for (int i = 0; i < n; i++) {
            float cv = 0.f;
            if (i < r && lane < c) cv = -g_GM[rows[w * 32 + i] * N + cols[w * 32 + lane]];
            C[i * 32 + lane] = cv;
        }
        __syncwarp();

        // Row reduction (lane = row; skewed scan, conflict-free).
        if (lane < n) {
            float m = 1e30f;
            #pragma unroll 4
            for (int k = 0; k < 32; k++) {
                int cidx = (k + lane) & 31;
                m = fminf(m, C[lane * 32 + cidx]);
            }
            u_w[lane + 1] = m;
        }
        __syncwarp();

        // Column reduction into register v, then tight-edge bitmask.
        float v = 0.f;
        unsigned tmask = 0;
        if (lane < n) {
            float m = 1e30f;
            #pragma unroll 4
            for (int i = 0; i < n; i++) m = fminf(m, C[i * 32 + lane] - u_w[i + 1]);
            v = m;
            #pragma unroll 4
            for (int i = 0; i < n; i++)
                if ((C[i * 32 + lane] - u_w[i + 1]) - v <= 0.0f) tmask |= 1u << i;
        }
        __syncwarp();

        // Greedy tight matching: pure ALU + REDUX, no LDS in the loop.
        int pcol = 0;
        unsigned rmmask = 0;
        for (int i = 1; i <= n; i++) {
            bool avail = (pcol == 0) && ((tmask >> (i - 1)) & 1);
            unsigned cand = avail ? (unsigned)lane : 0xffffffffu;
            unsigned cm = __reduce_min_sync(FULL, cand);
            if (cm != 0xffffffffu) {
                if ((int)cm == lane) pcol = i;
                rmmask |= 1u << (i - 1);
            }
        }
        p_w[lane + 1] = pcol;
        __syncwarp();
        float u_match = pcol ? u_w[pcol] : 0.f;

        // Augmenting phases: deferred potentials, shfl-served matching state.
        for (int f = 1; f <= n; f++) {
            if (rmmask & (1u << (f - 1))) continue;
            float uf = u_w[f];
            float d = (lane < n) ? (C[(f - 1) * 32 + lane] - uf) - v : 1e30f;
            int pred = 0;
            bool vis = false;
            int jf = 0; float Df = 0.f;

            for (int g = 0; g <= 32; g++) {
                unsigned key = vis ? 0xffffffffu : fkey(d);
                unsigned rmin = __reduce_min_sync(FULL, key);
                unsigned ball = __ballot_sync(FULL, key == rmin);
                int win = __ffs(ball) - 1;
                int   i1  = __shfl_sync(FULL, pcol, win);
                float ui1 = __shfl_sync(FULL, u_match, win);
                float dmin = unfkey(rmin);
                if (i1 == 0) { jf = win + 1; Df = dmin; break; }
                if (lane == win) vis = true;
                float cij = C[(i1 - 1) * 32 + lane];
                if (!vis && lane < n) {
                    float cand = dmin + ((cij - ui1) - v);
                    if (cand < d) { d = cand; pred = win + 1; }
                }
            }

            if (vis) {
                u_w[pcol] += Df - d;
                u_match   += Df - d;
                v += d - Df;
            }
            if (lane == 0) u_w[f] += Df;
            way_w[lane + 1] = pred;
            __syncwarp();

            if (lane == 0 && jf) {
                int jj = jf;
                while (jj) {
                    int jp = way_w[jj];
                    p_w[jj] = (jp == 0) ? f : p_w[jp];
                    jj = jp;
                }
            }
            __syncwarp();
            int np = p_w[lane + 1];
            if (np != pcol) { pcol = np; u_match = u_w[pcol]; }
        }

        float s = 0.f;
        if (lane < n) { int pr = p_w[lane + 1]; s = C[(pr - 1) * 32 + lane]; }
        #pragma unroll
        for (int o = 16; o; o >>= 1) s += __shfl_xor_sync(FULL, s, o);
        val = -s;
    }
    if (lane == 0) vals[w] = val;
    __syncthreads();

    if (tid == 0) {
        float tot = 0.f;
        for (int L = 0; L < 16; L++) tot += vals[L];
        out[0] = tot * (1.0f / N);
    }
}

// ---------------------------------------------------------------------------
extern "C" void kernel_launch(void* const* d_in, const int* in_sizes, int n_in,
                              void* d_out, int out_size) {
    const float* f1 = (const float*)d_in[0];
    const float* f2 = (const float*)d_in[1];
    const int*   t1 = (const int*)d_in[2];
    const int*   t2 = (const int*)d_in[3];
    float* out = (float*)d_out;

    dotsq_kernel<<<dim3(2, 2, KSLICES + 2), 256>>>(f1, f2);
    gm_kernel<<<64, 256>>>(t1, t2);

    size_t smem_assign = (size_t)16 * 1024 * 4          // tiles
                       + 2 * 16 * 32 * 4                // rows, cols
                       + 3 * 16 * 34 * 4                // u, p, way
                       + 2 * 128 * 4                    // t1s, t2s
                       + 32 * 4 + 16 * 4 + 16;          // rc, vals, s_need + pad
    cudaFuncSetAttribute(assign_kernel,
                         cudaFuncAttributeMaxDynamicSharedMemorySize, (int)smem_assign);
    assign_kernel<<<1, 512, smem_assign>>>(t1, t2, out);
}

// round 13
// speedup vs baseline: 23.0163x; 1.1220x over previous
#include <cuda_runtime.h>

#define N 128
#define D 8192
#define KSLICES 128
#define KSLICE (D / KSLICES)   // 64
#define KCHUNK 16
#define NCHUNKS (KSLICE / KCHUNK)  // 4

typedef unsigned long long ull;

__device__ float g_sq1[N], g_sq2[N];
__device__ float g_part[KSLICES * N * N];
__device__ float g_GM[N * N];
__device__ int   g_flag;           // nonzero => cross-label GM entry != 0

// ---------------------------------------------------------------------------
// K1: fused split-K GEMM + row norms.
// grid (1,1,136): z<128 -> GEMM: full 128x128 tile, 64-K slice, 256 threads,
//   8x8 outputs/thread, transposed smem [k][i], f32x2 FMA, double-buffered.
//   z>=128 -> 8 norm blocks (32 rows each, warp per 4 rows).
// ---------------------------------------------------------------------------
__global__ void __launch_bounds__(256) dotsq_kernel(const float* __restrict__ f1,
                                                    const float* __restrict__ f2) {
    if (blockIdx.z >= KSLICES) {
        // ---- norm path ----
        int flat = blockIdx.z - KSLICES;      // 0..7
        int tid  = threadIdx.x;
        int wid  = tid >> 5, lane = tid & 31;
        if (flat == 0 && tid == 0) g_flag = 0;
        #pragma unroll
        for (int rr = 0; rr < 4; rr++) {
            int row = flat * 32 + wid * 4 + rr;   // 0..255
            const float* f = (row < N) ? (f1 + (size_t)row * D)
                                       : (f2 + (size_t)(row - N) * D);
            const float4* f4 = (const float4*)f;
            float s = 0.f;
            #pragma unroll 8
            for (int it = 0; it < D / 4 / 32; it++) {
                float4 v = f4[lane + it * 32];
                s += v.x * v.x + v.y * v.y + v.z * v.z + v.w * v.w;
            }
            #pragma unroll
            for (int o = 16; o; o >>= 1) s += __shfl_xor_sync(0xffffffffu, s, o);
            if (lane == 0) { if (row < N) g_sq1[row] = s; else g_sq2[row - N] = s; }
        }
        return;
    }

    // ---- GEMM path: C[128][128] += A[128][64] * B[128][64]^T (this slice) ----
    __shared__ float As[2][KCHUNK][128];   // [k][i], i contiguous
    __shared__ float Bs[2][KCHUNK][128];   // [k][j], j contiguous

    int tid = threadIdx.x;                 // 0..255
    int ix = tid & 15;                     // i group: rows ix*4..+3 and +64
    int jy = tid >> 4;                     // j group: cols jy*4..+3 and +64
    int k0 = blockIdx.z * KSLICE;

    int lrow = tid & 127;                  // load row (i or j)
    int lkq  = (tid >> 7) * 4;             // load k offset (0 or 4)

    ull acc[8][4];
    #pragma unroll
    for (int m = 0; m < 8; m++)
        #pragma unroll
        for (int p = 0; p < 4; p++) acc[m][p] = 0ull;

    // prolog: load + stage chunk 0
    float4 pa0 = *(const float4*)&f1[(size_t)lrow * D + k0 + lkq];
    float4 pa1 = *(const float4*)&f1[(size_t)lrow * D + k0 + lkq + 8];
    float4 pb0 = *(const float4*)&f2[(size_t)lrow * D + k0 + lkq];
    float4 pb1 = *(const float4*)&f2[(size_t)lrow * D + k0 + lkq + 8];
    As[0][lkq + 0][lrow] = pa0.x; As[0][lkq + 1][lrow] = pa0.y;
    As[0][lkq + 2][lrow] = pa0.z; As[0][lkq + 3][lrow] = pa0.w;
    As[0][lkq + 8][lrow] = pa1.x; As[0][lkq + 9][lrow] = pa1.y;
    As[0][lkq + 10][lrow] = pa1.z; As[0][lkq + 11][lrow] = pa1.w;
    Bs[0][lkq + 0][lrow] = pb0.x; Bs[0][lkq + 1][lrow] = pb0.y;
    Bs[0][lkq + 2][lrow] = pb0.z; Bs[0][lkq + 3][lrow] = pb0.w;
    Bs[0][lkq + 8][lrow] = pb1.x; Bs[0][lkq + 9][lrow] = pb1.y;
    Bs[0][lkq + 10][lrow] = pb1.z; Bs[0][lkq + 11][lrow] = pb1.w;
    __syncthreads();

    #pragma unroll
    for (int c = 0; c < NCHUNKS; c++) {
        int buf = c & 1;
        // prefetch next chunk to registers
        if (c + 1 < NCHUNKS) {
            int kc = k0 + (c + 1) * KCHUNK + lkq;
            pa0 = *(const float4*)&f1[(size_t)lrow * D + kc];
            pa1 = *(const float4*)&f1[(size_t)lrow * D + kc + 8];
            pb0 = *(const float4*)&f2[(size_t)lrow * D + kc];
            pb1 = *(const float4*)&f2[(size_t)lrow * D + kc + 8];
        }

        #pragma unroll
        for (int k = 0; k < KCHUNK; k++) {
            float4 alo = *(const float4*)&As[buf][k][ix * 4];
            float4 ahi = *(const float4*)&As[buf][k][ix * 4 + 64];
            float4 blo = *(const float4*)&Bs[buf][k][jy * 4];
            float4 bhi = *(const float4*)&Bs[buf][k][jy * 4 + 64];
            ull b01, b23, b45, b67;
            asm("mov.b64 %0, {%1, %2};" : "=l"(b01) : "f"(blo.x), "f"(blo.y));
            asm("mov.b64 %0, {%1, %2};" : "=l"(b23) : "f"(blo.z), "f"(blo.w));
            asm("mov.b64 %0, {%1, %2};" : "=l"(b45) : "f"(bhi.x), "f"(bhi.y));
            asm("mov.b64 %0, {%1, %2};" : "=l"(b67) : "f"(bhi.z), "f"(bhi.w));
            float av[8] = {alo.x, alo.y, alo.z, alo.w, ahi.x, ahi.y, ahi.z, ahi.w};
            #pragma unroll
            for (int m = 0; m < 8; m++) {
                ull aa;
                asm("mov.b64 %0, {%1, %1};" : "=l"(aa) : "f"(av[m]));
                asm("fma.rn.f32x2 %0, %1, %2, %0;" : "+l"(acc[m][0]) : "l"(aa), "l"(b01));
                asm("fma.rn.f32x2 %0, %1, %2, %0;" : "+l"(acc[m][1]) : "l"(aa), "l"(b23));
                asm("fma.rn.f32x2 %0, %1, %2, %0;" : "+l"(acc[m][2]) : "l"(aa), "l"(b45));
                asm("fma.rn.f32x2 %0, %1, %2, %0;" : "+l"(acc[m][3]) : "l"(aa), "l"(b67));
            }
        }
        __syncthreads();

        if (c + 1 < NCHUNKS) {
            int nb = (c + 1) & 1;
            As[nb][lkq + 0][lrow] = pa0.x; As[nb][lkq + 1][lrow] = pa0.y;
            As[nb][lkq + 2][lrow] = pa0.z; As[nb][lkq + 3][lrow] = pa0.w;
            As[nb][lkq + 8][lrow] = pa1.x; As[nb][lkq + 9][lrow] = pa1.y;
            As[nb][lkq + 10][lrow] = pa1.z; As[nb][lkq + 11][lrow] = pa1.w;
            Bs[nb][lkq + 0][lrow] = pb0.x; Bs[nb][lkq + 1][lrow] = pb0.y;
            Bs[nb][lkq + 2][lrow] = pb0.z; Bs[nb][lkq + 3][lrow] = pb0.w;
            Bs[nb][lkq + 8][lrow] = pb1.x; Bs[nb][lkq + 9][lrow] = pb1.y;
            Bs[nb][lkq + 10][lrow] = pb1.z; Bs[nb][lkq + 11][lrow] = pb1.w;
            __syncthreads();
        }
    }

    // epilogue: unpack and store
    #pragma unroll
    for (int m = 0; m < 8; m++) {
        int gi = (m < 4) ? (ix * 4 + m) : (ix * 4 + 64 + (m - 4));
        float4 o;
        float lo, hi;
        asm("mov.b64 {%0,%1}, %2;" : "=f"(lo), "=f"(hi) : "l"(acc[m][0])); o.x = lo; o.y = hi;
        asm("mov.b64 {%0,%1}, %2;" : "=f"(lo), "=f"(hi) : "l"(acc[m][1])); o.z = lo; o.w = hi;
        *(float4*)&g_part[blockIdx.z * (N * N) + (size_t)gi * N + jy * 4] = o;
        asm("mov.b64 {%0,%1}, %2;" : "=f"(lo), "=f"(hi) : "l"(acc[m][2])); o.x = lo; o.y = hi;
        asm("mov.b64 {%0,%1}, %2;" : "=f"(lo), "=f"(hi) : "l"(acc[m][3])); o.z = lo; o.w = hi;
        *(float4*)&g_part[blockIdx.z * (N * N) + (size_t)gi * N + jy * 4 + 64] = o;
    }
}

// ---------------------------------------------------------------------------
// K2: finalize GM[i][j]; flag if any cross-label GM entry is nonzero.
// ---------------------------------------------------------------------------
__global__ void gm_kernel(const int* __restrict__ t1, const int* __restrict__ t2) {
    int idx = blockIdx.x * 256 + threadIdx.x;
    int i = idx >> 7, j = idx & (N - 1);
    float dot = 0.f;
    #pragma unroll 16
    for (int s = 0; s < KSLICES; s++) dot += g_part[s * (N * N) + idx];
    float d2 = g_sq1[i] - 2.f * dot + g_sq2[j];
    bool same = (t1[i] == t2[j]);
    float gm = same ? fmaxf(0.f, d2) : fmaxf(0.f, 200.f - d2);
    g_GM[idx] = gm;
    if (!same && gm != 0.f) atomicOr(&g_flag, 1);
}

// ---------------------------------------------------------------------------
// order-preserving float <-> u32 keys for min reductions
// ---------------------------------------------------------------------------
__device__ __forceinline__ unsigned fkey(float f) {
    unsigned u = __float_as_uint(f);
    return (u & 0x80000000u) ? ~u : (u | 0x80000000u);
}
__device__ __forceinline__ float unfkey(unsigned k) {
    return __uint_as_float((k & 0x80000000u) ? (k ^ 0x80000000u) : ~k);
}

// ---------------------------------------------------------------------------
// K3: block-decomposed assignment (one warp per label, 16 warps in one CTA).
// Warp 0 runs the full 128x128 fallback if the precondition fails.
// ---------------------------------------------------------------------------
__global__ void assign_kernel(const int* __restrict__ t1, const int* __restrict__ t2,
                              float* __restrict__ out) {
    extern __shared__ unsigned char raw[];
    float* tile    = (float*)raw;                 // 16 * 1024 floats (64 KB)
    int*   rows    = (int*)(tile + 16 * 1024);    // 16 * 32 (fallback: rm_s)
    int*   cols    = rows + 16 * 32;              // 16 * 32
    float* u_all   = (float*)(cols + 16 * 32);    // 16 * 34 (fallback: u_s)
    int*   p_all   = (int*)(u_all + 16 * 34);     // 16 * 34 (fallback: p_s)
    int*   way_all = p_all + 16 * 34;             // 16 * 34 (fallback: way_s)
    int*   t1s     = way_all + 16 * 34;           // 128
    int*   t2s     = t1s + 128;                   // 128
    int*   rc      = t2s + 128;                   // 32
    float* vals    = (float*)(rc + 32);           // 16
    int*   s_need  = (int*)(vals + 16);           // 1

    const unsigned FULL = 0xffffffffu;
    int tid = threadIdx.x, lane = tid & 31, w = tid >> 5;

    if (tid < 128) { t1s[tid] = t1[tid]; t2s[tid] = t2[tid]; }
    __syncthreads();

    int r = 0, c = 0;
    #pragma unroll
    for (int ch = 0; ch < 4; ch++) {
        int e1 = t1s[ch * 32 + lane];
        unsigned b1 = __ballot_sync(FULL, e1 == w);
        if (e1 == w) {
            int pos = r + __popc(b1 & ((1u << lane) - 1u));
            if (pos < 32) rows[w * 32 + pos] = ch * 32 + lane;
        }
        r += __popc(b1);
        int e2 = t2s[ch * 32 + lane];
        unsigned b2 = __ballot_sync(FULL, e2 == w);
        if (e2 == w) {
            int pos = c + __popc(b2 & ((1u << lane) - 1u));
            if (pos < 32) cols[w * 32 + pos] = ch * 32 + lane;
        }
        c += __popc(b2);
    }
    if (lane == 0) { rc[w * 2] = r; rc[w * 2 + 1] = c; }
    __syncthreads();

    if (tid == 0) {
        int need = (g_flag != 0);
        int sr = 0, sc = 0;
        for (int L = 0; L < 16; L++) {
            int rr = rc[L * 2], cc = rc[L * 2 + 1];
            sr += rr; sc += cc;
            if (rr > 32 || cc > 32) need = 1;
        }
        if (sr != N || sc != N) need = 1;
        s_need[0] = need;
    }
    __syncthreads();

    // ---------------- fallback: full 128x128 single-warp Hungarian ----------
    if (s_need[0]) {
        if (w != 0) return;
        float* cost  = tile;
        float* u_s   = u_all;
        int*   p_s   = p_all;
        int*   way_s = way_all;
        int*   rm_s  = rows;

        for (int idx = lane; idx < N * N; idx += 32) cost[idx] = -g_GM[idx];
        for (int idx = lane; idx <= N; idx += 32) { p_s[idx] = 0; way_s[idx] = 0; rm_s[idx] = 0; }
        __syncwarp();

        #pragma unroll
        for (int t = 0; t < 4; t++) {
            int rr = lane + 32 * t;
            float m = 1e30f;
            #pragma unroll 4
            for (int cc = 0; cc < N; cc++) {
                int ccc = (cc + lane) & (N - 1);
                m = fminf(m, cost[rr * N + ccc]);
            }
            u_s[rr + 1] = m;
        }
        __syncwarp();

        float v4[4];
        #pragma unroll
        for (int t = 0; t < 4; t++) {
            int cc = lane + 32 * t;
            float m = 1e30f;
            for (int rr = 0; rr < N; rr++) m = fminf(m, cost[rr * N + cc] - u_s[rr + 1]);
            v4[t] = m;
        }
        __syncwarp();

        for (int i = 1; i <= N; i++) {
            unsigned cand = 0xffffffffu;
            float ui = u_s[i];
            #pragma unroll
            for (int t = 0; t < 4; t++) {
                int cc = lane + 32 * t;
                if (p_s[cc + 1] == 0) {
                    float cur = (cost[(i - 1) * N + cc] - ui) - v4[t];
                    if (cur <= 0.0f) cand = min(cand, (unsigned)cc);
                }
            }
            unsigned cm = __reduce_min_sync(FULL, cand);
            if (cm != 0xffffffffu && lane == 0) { p_s[cm + 1] = i; rm_s[i] = 1; }
            __syncwarp();
        }

        for (int i = 1; i <= N; i++) {
            if (rm_s[i]) continue;
            float minv[4] = {1e30f, 1e30f, 1e30f, 1e30f};
            unsigned usedmask = 0;
            if (lane == 0) p_s[0] = i;
            int j0 = 0;
            __syncwarp();

            for (int guard = 0; guard < N + 2; guard++) {
                if (j0 > 0) {
                    int cc = j0 - 1;
                    if ((cc & 31) == lane) usedmask |= 1u << (cc >> 5);
                }
                int i0 = p_s[j0];
                float ui0 = u_s[i0];
                float best = 1e30f; int bestc = 0;
                #pragma unroll
                for (int t = 0; t < 4; t++) {
                    if (!((usedmask >> t) & 1)) {
                        int cc = lane + 32 * t;
                        float cur = (cost[(i0 - 1) * N + cc] - ui0) - v4[t];
                        if (cur < minv[t]) { minv[t] = cur; way_s[cc + 1] = j0; }
                        if (minv[t] < best) { best = minv[t]; bestc = cc; }
                    }
                }
                unsigned key = fkey(best);
                unsigned rmin = __reduce_min_sync(FULL, key);
                unsigned ball = __ballot_sync(FULL, key == rmin);
                int win = __ffs(ball) - 1;
                float delta = __shfl_sync(FULL, best, win);
                int j1 = __shfl_sync(FULL, bestc, win) + 1;

                #pragma unroll
                for (int t = 0; t < 4; t++) {
                    if ((usedmask >> t) & 1) {
                        v4[t] -= delta;
                        int pr = p_s[lane + 32 * t + 1];
                        u_s[pr] += delta;
                    } else {
                        minv[t] -= delta;
                    }
                }
                if (lane == 0) u_s[i] += delta;
                j0 = j1;
                __syncwarp();
                if (p_s[j0] == 0) break;
            }

            if (lane == 0) {
                int jj = j0;
                while (jj) { int j1 = way_s[jj]; p_s[jj] = p_s[j1]; jj = j1; }
                rm_s[i] = 1;
            }
            __syncwarp();
        }

        float s = 0.f;
        #pragma unroll
        for (int t = 0; t < 4; t++) {
            int cc = lane + 32 * t;
            int rr = p_s[cc + 1];
            s += cost[(rr - 1) * N + cc];
        }
        #pragma unroll
        for (int o = 16; o; o >>= 1) s += __shfl_xor_sync(FULL, s, o);
        if (lane == 0) out[0] = -s * (1.0f / N);
        return;
    }

    // ---------------- fast path: per-label JV Hungarian -----------------
    int n = max(r, c);
    float val = 0.f;
    if (r > 0 && c > 0) {
        float* C     = tile + w * 1024;       // C[i*32 + j]
        float* u_w   = u_all + w * 34;        // rows 1..n
        int*   p_w   = p_all + w * 34;        // col j (1..n) -> matched row (0 free)
        int*   way_w = way_all + w * 34;

        #pragma unroll 4
        for (int i = 0; i < n; i++) {
            float cv = 0.f;
            if (i < r && lane < c) cv = -g_GM[rows[w * 32 + i] * N + cols[w * 32 + lane]];
            C[i * 32 + lane] = cv;
        }
        __syncwarp();

        if (lane < n) {
            float m = 1e30f;
            #pragma unroll 4
            for (int k = 0; k < 32; k++) {
                int cidx = (k + lane) & 31;
                m = fminf(m, C[lane * 32 + cidx]);
            }
            u_w[lane + 1] = m;
        }
        __syncwarp();

        float v = 0.f;
        unsigned tmask = 0;
        if (lane < n) {
            float m = 1e30f;
            #pragma unroll 4
            for (int i = 0; i < n; i++) m = fminf(m, C[i * 32 + lane] - u_w[i + 1]);
            v = m;
            #pragma unroll 4
            for (int i = 0; i < n; i++)
                if ((C[i * 32 + lane] - u_w[i + 1]) - v <= 0.0f) tmask |= 1u << i;
        }
        __syncwarp();

        int pcol = 0;
        unsigned rmmask = 0;
        for (int i = 1; i <= n; i++) {
            bool avail = (pcol == 0) && ((tmask >> (i - 1)) & 1);
            unsigned cand = avail ? (unsigned)lane : 0xffffffffu;
            unsigned cm = __reduce_min_sync(FULL, cand);
            if (cm != 0xffffffffu) {
                if ((int)cm == lane) pcol = i;
                rmmask |= 1u << (i - 1);
            }
        }
        p_w[lane + 1] = pcol;
        __syncwarp();
        float u_match = pcol ? u_w[pcol] : 0.f;

        for (int f = 1; f <= n; f++) {
            if (rmmask & (1u << (f - 1))) continue;
            float uf = u_w[f];
            float d = (lane < n) ? (C[(f - 1) * 32 + lane] - uf) - v : 1e30f;
            int pred = 0;
            bool vis = false;
            int jf = 0; float Df = 0.f;

            for (int g = 0; g <= 32; g++) {
                unsigned key = vis ? 0xffffffffu : fkey(d);
                unsigned rmin = __reduce_min_sync(FULL, key);
                unsigned ball = __ballot_sync(FULL, key == rmin);
                int win = __ffs(ball) - 1;
                int   i1  = __shfl_sync(FULL, pcol, win);
                float ui1 = __shfl_sync(FULL, u_match, win);
                float dmin = unfkey(rmin);
                if (i1 == 0) { jf = win + 1; Df = dmin; break; }
                if (lane == win) vis = true;
                float cij = C[(i1 - 1) * 32 + lane];
                if (!vis && lane < n) {
                    float cand = dmin + ((cij - ui1) - v);
                    if (cand < d) { d = cand; pred = win + 1; }
                }
            }

            if (vis) {
                u_w[pcol] += Df - d;
                u_match   += Df - d;
                v += d - Df;
            }
            if (lane == 0) u_w[f] += Df;
            way_w[lane + 1] = pred;
            __syncwarp();

            if (lane == 0 && jf) {
                int jj = jf;
                while (jj) {
                    int jp = way_w[jj];
                    p_w[jj] = (jp == 0) ? f : p_w[jp];
                    jj = jp;
                }
            }
            __syncwarp();
            int np = p_w[lane + 1];
            if (np != pcol) { pcol = np; u_match = u_w[pcol]; }
        }

        float s = 0.f;
        if (lane < n) { int pr = p_w[lane + 1]; s = C[(pr - 1) * 32 + lane]; }
        #pragma unroll
        for (int o = 16; o; o >>= 1) s += __shfl_xor_sync(FULL, s, o);
        val = -s;
    }
    if (lane == 0) vals[w] = val;
    __syncthreads();

    if (tid == 0) {
        float tot = 0.f;
        for (int L = 0; L < 16; L++) tot += vals[L];
        out[0] = tot * (1.0f / N);
    }
}

// ---------------------------------------------------------------------------
extern "C" void kernel_launch(void* const* d_in, const int* in_sizes, int n_in,
                              void* d_out, int out_size) {
    const float* f1 = (const float*)d_in[0];
    const float* f2 = (const float*)d_in[1];
    const int*   t1 = (const int*)d_in[2];
    const int*   t2 = (const int*)d_in[3];
    float* out = (float*)d_out;

    dotsq_kernel<<<dim3(1, 1, KSLICES + 8), 256>>>(f1, f2);
    gm_kernel<<<64, 256>>>(t1, t2);

    size_t smem_assign = (size_t)16 * 1024 * 4          // tiles
                       + 2 * 16 * 32 * 4                // rows, cols
                       + 3 * 16 * 34 * 4                // u, p, way
                       + 2 * 128 * 4                    // t1s, t2s
                       + 32 * 4 + 16 * 4 + 16;          // rc, vals, s_need + pad
    cudaFuncSetAttribute(assign_kernel,
                         cudaFuncAttributeMaxDynamicSharedMemorySize, (int)smem_assign);
    assign_kernel<<<1, 512, smem_assign>>>(t1, t2, out);
}